// round 9
// baseline (speedup 1.0000x reference)
#include <cuda_runtime.h>
#include <math.h>
#include <stdint.h>

// Problem constants
#define BB    64
#define CC    512
#define HH    8
#define HD    64
#define FREQE 256
#define ROWS  4096   // B*N == N*M
#define WSLOT (CC * CC)

// ---------------------------------------------------------------------------
// Scratch (device globals; no allocation allowed)
// ---------------------------------------------------------------------------
__device__ float g_pe [ROWS * CC];
__device__ float g_q  [ROWS * CC];
__device__ float g_k  [ROWS * CC];
__device__ float g_v  [ROWS * CC];
__device__ float g_x  [ROWS * CC];
__device__ float g_emb[ROWS * FREQE];
__device__ float g_hid[ROWS * CC];
__device__ float g_bqkv[3 * CC];
__device__ float g_wt [6 * CC * CC];    // transposed W1,W2,Wq,Wk,Wv,Wo (fp32)

__device__ __forceinline__ uint32_t to_tf32(float x) {
    uint32_t u;
    asm("cvt.rna.tf32.f32 %0, %1;" : "=r"(u) : "f"(x));
    return u;
}

__device__ __forceinline__ uint32_t smem_u32(const void* p) {
    uint32_t a;
    asm("{ .reg .u64 t; cvta.to.shared.u64 t, %1; cvt.u32.u64 %0, t; }"
        : "=r"(a) : "l"(p));
    return a;
}

__device__ __forceinline__ void cp16(uint32_t dst, const void* src) {
    asm volatile("cp.async.cg.shared.global [%0], [%1], 16;" :: "r"(dst), "l"(src));
}
#define CP_COMMIT() asm volatile("cp.async.commit_group;" ::: "memory")
#define CP_WAIT(n)  asm volatile("cp.async.wait_group %0;" :: "n"(n) : "memory")

// ---------------------------------------------------------------------------
// Node 1 — prep: embedding + 6 weight transposes + fused qkv bias.
//   blocks [0, 4096)      : sinusoidal embedding -> g_emb
//   blocks [4096, 5632)   : weight transposes -> g_wt
//   blocks [5632, 5638)   : fused qkv bias -> g_bqkv
// ---------------------------------------------------------------------------
#define PREP_BLOCKS (4096 + 1536 + 6)

__global__ __launch_bounds__(256) void prep_kernel(
    const float* __restrict__ qpos,
    const float* __restrict__ W1, const float* __restrict__ W2,
    const float* __restrict__ Wq, const float* __restrict__ Wk,
    const float* __restrict__ Wv, const float* __restrict__ Wo,
    const float* __restrict__ bq, const float* __restrict__ bv)
{
    int bid = blockIdx.x;
    int t = threadIdx.x;

    if (bid < 4096) {                       // embedding
        int idx = bid * 256 + t;
        int p = idx >> 8;
        int j = idx & 255;
        float tp = qpos[p];
        int jj = j & 127;
        float f = expf(-9.210340371976184f * (float)jj * (1.0f / 128.0f));
        float a = tp * f;
        g_emb[idx] = (j < 128) ? cosf(a) : sinf(a);
        return;
    }
    if (bid < 5632) {                       // weight transposes
        int bid2 = bid - 4096;
        int slot = bid2 >> 8;               // 0..5
        int r    = bid2 & 255;
        int k0 = (r & 15) * 32;
        int n0 = (r >> 4) * 32;
        int K = (slot == 0) ? FREQE : CC;
        if (k0 >= K) return;

        const float* W = (slot == 0) ? W1 : (slot == 1) ? W2 : (slot == 2) ? Wq
                       : (slot == 3) ? Wk : (slot == 4) ? Wv : Wo;

        __shared__ float sm[32][33];
        int tx = t & 31, ty = t >> 5;
#pragma unroll
        for (int i = 0; i < 4; i++) {
            int rr = ty + i * 8;
            sm[rr][tx] = W[(size_t)(k0 + rr) * CC + n0 + tx];
        }
        __syncthreads();
#pragma unroll
        for (int i = 0; i < 4; i++) {
            int rr = ty + i * 8;
            g_wt[(size_t)slot * WSLOT + (size_t)(n0 + rr) * K + k0 + tx] = sm[tx][rr];
        }
        return;
    }
    {                                       // bias fuse
        int i = (bid - 5632) * 256 + t;     // 0..1535
        float v = 0.0f;
        if (i < 512) v = bq[i];
        else if (i >= 1024) v = bv[i - 1024];
        g_bqkv[i] = v;
    }
}

// ---------------------------------------------------------------------------
// 1xTF32 GEMM body, BM=64 x BN=128 x BK=32, 8 warps of 32x32.
// In-kernel cvt.rna.tf32 on fragment loads (round-6 numerics).
// epi: 0=+bias ; 1=silu(+bias) ; 2=+bias+resid ; 3=QKV split {Cf,C2,C3}
// ---------------------------------------------------------------------------
#define TPAD 36
#define ATILE (64 * TPAD * 4)           // 9216 B
#define BTILE (128 * TPAD * 4)          // 18432 B
#define TSMEM (2 * ATILE + 2 * BTILE)   // 55296 B

#define MMA1688T(d, a, b) \
    asm volatile( \
        "mma.sync.aligned.m16n8k8.row.col.f32.tf32.tf32.f32 " \
        "{%0,%1,%2,%3}, {%4,%5,%6,%7}, {%8,%9}, {%0,%1,%2,%3};" \
        : "+f"((d)[0]), "+f"((d)[1]), "+f"((d)[2]), "+f"((d)[3]) \
        : "r"((a)[0]), "r"((a)[1]), "r"((a)[2]), "r"((a)[3]), \
          "r"((b)[0]), "r"((b)[1]))

__device__ __forceinline__ void gemm_body(
    const float* __restrict__ A, const float* __restrict__ Bt,
    const float* __restrict__ bias, const float* __restrict__ resid,
    float* __restrict__ Cf, float* __restrict__ C2, float* __restrict__ C3,
    int K, int epi, int bx, int by, float* smf)
{
    uint32_t sbase = smem_u32(smf);
    int t = threadIdx.x, lane = t & 31, wid = t >> 5;
    int wm = wid >> 2;        // 0..1 -> m offset wm*32
    int wn = wid & 3;         // 0..3 -> n offset wn*32
    int m0 = by * 64, n0 = bx * 128;
    int gr = lane >> 2, gc = lane & 3;

    float acc[2][4][4];
#pragma unroll
    for (int mi = 0; mi < 2; mi++)
#pragma unroll
        for (int ni = 0; ni < 4; ni++)
#pragma unroll
            for (int j = 0; j < 4; j++) acc[mi][ni][j] = 0.0f;

    int nch = K >> 5;

    auto load_chunk = [&](int ch, int buf) {
        int k0 = ch << 5;
#pragma unroll
        for (int i = 0; i < 2; i++) {       // A: 64 rows x 8 chunks
            int idx = t + i * 256;
            int row = idx >> 3;
            int c   = idx & 7;
            uint32_t off = (uint32_t)(row * TPAD * 4 + c * 16);
            cp16(sbase + buf * ATILE + off,
                 A + (size_t)(m0 + row) * K + k0 + c * 4);
        }
#pragma unroll
        for (int i = 0; i < 4; i++) {       // B: 128 rows x 8 chunks
            int idx = t + i * 256;
            int row = idx >> 3;
            int c   = idx & 7;
            uint32_t off = (uint32_t)(row * TPAD * 4 + c * 16);
            cp16(sbase + 2 * ATILE + buf * BTILE + off,
                 Bt + (size_t)(n0 + row) * K + k0 + c * 4);
        }
        CP_COMMIT();
    };

    load_chunk(0, 0);
    load_chunk(1, 1);

    for (int ch = 0; ch < nch; ch++) {
        if (ch + 1 < nch) { CP_WAIT(1); } else { CP_WAIT(0); }
        __syncthreads();

        int buf = ch & 1;
        const float* sA = smf + (buf * ATILE >> 2);
        const float* sB = smf + ((2 * ATILE + buf * BTILE) >> 2);

#pragma unroll
        for (int ks = 0; ks < 4; ks++) {
            int kk = ks * 8;
            uint32_t af[2][4], bf[4][2];
#pragma unroll
            for (int mi = 0; mi < 2; mi++) {
                int base = (wm * 32 + mi * 16 + gr) * TPAD + kk;
                af[mi][0] = to_tf32(sA[base + gc]);
                af[mi][1] = to_tf32(sA[base + 8 * TPAD + gc]);
                af[mi][2] = to_tf32(sA[base + gc + 4]);
                af[mi][3] = to_tf32(sA[base + 8 * TPAD + gc + 4]);
            }
#pragma unroll
            for (int ni = 0; ni < 4; ni++) {
                int base = (wn * 32 + ni * 8 + gr) * TPAD + kk;
                bf[ni][0] = to_tf32(sB[base + gc]);
                bf[ni][1] = to_tf32(sB[base + gc + 4]);
            }
#pragma unroll
            for (int mi = 0; mi < 2; mi++)
#pragma unroll
                for (int ni = 0; ni < 4; ni++)
                    MMA1688T(acc[mi][ni], af[mi], bf[ni]);
        }
        __syncthreads();
        if (ch + 2 < nch) load_chunk(ch + 2, buf);
    }

    // Epilogue
#pragma unroll
    for (int mi = 0; mi < 2; mi++) {
#pragma unroll
        for (int ni = 0; ni < 4; ni++) {
            int row0 = m0 + wm * 32 + mi * 16 + gr;
            int col  = n0 + wn * 32 + ni * 8 + gc * 2;
#pragma unroll
            for (int half = 0; half < 2; half++) {
                int row = row0 + half * 8;
                float v0 = acc[mi][ni][half * 2 + 0];
                float v1 = acc[mi][ni][half * 2 + 1];
                if (bias) { v0 += bias[col]; v1 += bias[col + 1]; }
                if (epi == 1) {
                    v0 = v0 / (1.0f + expf(-v0));
                    v1 = v1 / (1.0f + expf(-v1));
                }
                if (epi == 3) {
                    int seg = col >> 9;
                    float* dst = (seg == 0) ? Cf : (seg == 1) ? C2 : C3;
                    size_t o = (size_t)row * CC + (col & 511);
                    *(float2*)(dst + o) = make_float2(v0, v1);
                } else {
                    size_t o = (size_t)row * CC + col;
                    if (epi == 2) {
                        v0 += resid[o];
                        v1 += resid[o + 1];
                    }
                    *(float2*)(Cf + o) = make_float2(v0, v1);
                }
            }
        }
    }
}

// ---------------------------------------------------------------------------
// Node 2 — QKV (768 blocks) + MLP1 (256 blocks) fused; independent GEMMs.
// ---------------------------------------------------------------------------
__global__ __launch_bounds__(256, 2) void gemm_qkv_mlp1(
    const float* __restrict__ query, const float* __restrict__ b1)
{
    extern __shared__ float smf[];
    int bid = blockIdx.x;
    if (bid < 768) {
        gemm_body(query, g_wt + 2 * WSLOT, g_bqkv, nullptr,
                  g_q, g_k, g_v, CC, 3, bid % 12, bid / 12, smf);
    } else {
        int b2 = bid - 768;
        gemm_body(g_emb, g_wt + 0 * WSLOT, b1, nullptr,
                  g_hid, nullptr, nullptr, FREQE, 1, b2 & 3, b2 >> 2, smf);
    }
}

// Node 3 — MLP2
__global__ __launch_bounds__(256, 2) void gemm_mlp2(const float* __restrict__ b2)
{
    extern __shared__ float smf[];
    int bid = blockIdx.x;
    gemm_body(g_hid, g_wt + 1 * WSLOT, b2, nullptr,
              g_pe, nullptr, nullptr, CC, 0, bid & 3, bid >> 2, smf);
}

// Node 5 — output projection + bias + residual
__global__ __launch_bounds__(256, 2) void gemm_out(
    const float* __restrict__ bo, const float* __restrict__ query,
    float* __restrict__ out)
{
    extern __shared__ float smf[];
    int bid = blockIdx.x;
    gemm_body(g_x, g_wt + 5 * WSLOT, bo, query,
              out, nullptr, nullptr, CC, 2, bid & 3, bid >> 2, smf);
}

// ---------------------------------------------------------------------------
// Node 4 — fused attention, 4 batches per block: grid (16 bgroups, 8 heads).
// ---------------------------------------------------------------------------
#define ATTN_SMEM (4 * 64 * 68 * 4)

__global__ __launch_bounds__(256, 1) void attn_kernel() {
    extern __shared__ float kv[];      // staging: [4][64][68]
    __shared__ float qrow[4][64];
    __shared__ float s[4][64];

    int h   = blockIdx.y;
    int bg0 = blockIdx.x * 4;
    int t   = threadIdx.x;
    int bh  = t >> 6;
    int i   = t & 63;

    float kreg[64], vreg[64];

#pragma unroll
    for (int it = 0; it < 16; it++) {
        int slot = t + it * 256;
        int b  = slot >> 10;
        int m  = (slot >> 4) & 63;
        int d4 = slot & 15;
        float4 x = *(const float4*)(g_k + ((size_t)((bg0 + b) * 64 + m)) * 512 + h * 64 + d4 * 4);
        *(float4*)&kv[(b * 64 + m) * 68 + d4 * 4] = x;
    }
    __syncthreads();
#pragma unroll
    for (int d = 0; d < 64; d++) kreg[d] = kv[(bh * 64 + i) * 68 + d];
    __syncthreads();

#pragma unroll
    for (int it = 0; it < 16; it++) {
        int slot = t + it * 256;
        int b  = slot >> 10;
        int m  = (slot >> 4) & 63;
        int d4 = slot & 15;
        float4 x = *(const float4*)(g_v + ((size_t)((bg0 + b) * 64 + m)) * 512 + h * 64 + d4 * 4);
        *(float4*)&kv[(b * 64 + m) * 68 + d4 * 4] = x;
    }
    __syncthreads();
#pragma unroll
    for (int m = 0; m < 64; m++) vreg[m] = kv[(bh * 64 + m) * 68 + i];
    __syncthreads();

    for (int n = 0; n < 64; n++) {
        if (t < 64) {
            int b = t >> 4, w = t & 15;
            float4 qv = *(const float4*)(g_q + ((size_t)((bg0 + b) * 64 + n)) * 512 + h * 64 + w * 4);
            *(float4*)&qrow[b][w * 4] = qv;
        }
        __syncthreads();

        const float* pep = g_pe + ((size_t)(n * 64 + i)) * 512 + h * 64;
        float p = 0.0f;
#pragma unroll
        for (int d4 = 0; d4 < 16; d4++) {
            float4 pe4 = *(const float4*)(pep + d4 * 4);
            int d = d4 * 4;
            p = fmaf(qrow[bh][d + 0] * kreg[d + 0], pe4.x, p);
            p = fmaf(qrow[bh][d + 1] * kreg[d + 1], pe4.y, p);
            p = fmaf(qrow[bh][d + 2] * kreg[d + 2], pe4.z, p);
            p = fmaf(qrow[bh][d + 3] * kreg[d + 3], pe4.w, p);
        }
        s[bh][i] = p * 0.125f;
        __syncthreads();

        if (t < 128) {
            int w = t >> 5, lane = t & 31;
            float a  = s[w][lane];
            float c2 = s[w][lane + 32];
            float mx = fmaxf(a, c2);
#pragma unroll
            for (int off = 16; off > 0; off >>= 1)
                mx = fmaxf(mx, __shfl_xor_sync(0xffffffffu, mx, off));
            float e1 = __expf(a - mx), e2 = __expf(c2 - mx);
            float sm = e1 + e2;
#pragma unroll
            for (int off = 16; off > 0; off >>= 1)
                sm += __shfl_xor_sync(0xffffffffu, sm, off);
            float inv = 1.0f / sm;
            s[w][lane]      = e1 * inv;
            s[w][lane + 32] = e2 * inv;
        }
        __syncthreads();

        float xv = 0.0f;
#pragma unroll
        for (int m = 0; m < 64; m++)
            xv = fmaf(s[bh][m], vreg[m], xv);
        size_t o = ((size_t)((bg0 + bh) * 64 + n)) * 512 + h * 64 + i;
        g_x[o] = xv;
        __syncthreads();
    }
}

// ---------------------------------------------------------------------------
// Launch — 5 nodes, single stream, no events.
// ---------------------------------------------------------------------------
extern "C" void kernel_launch(void* const* d_in, const int* in_sizes, int n_in,
                              void* d_out, int out_size)
{
    const float* query = (const float*)d_in[0];
    const float* qpos  = (const float*)d_in[1];
    const float* Wq    = (const float*)d_in[2];
    const float* bq    = (const float*)d_in[3];
    const float* Wk    = (const float*)d_in[4];
    const float* Wv    = (const float*)d_in[5];
    const float* bv    = (const float*)d_in[6];
    const float* Wo    = (const float*)d_in[7];
    const float* bo    = (const float*)d_in[8];
    const float* W1    = (const float*)d_in[9];
    const float* b1    = (const float*)d_in[10];
    const float* W2    = (const float*)d_in[11];
    const float* b2    = (const float*)d_in[12];
    float* out = (float*)d_out;

    static bool init = false;
    if (!init) {
        cudaFuncSetAttribute(gemm_qkv_mlp1, cudaFuncAttributeMaxDynamicSharedMemorySize, TSMEM);
        cudaFuncSetAttribute(gemm_mlp2,     cudaFuncAttributeMaxDynamicSharedMemorySize, TSMEM);
        cudaFuncSetAttribute(gemm_out,      cudaFuncAttributeMaxDynamicSharedMemorySize, TSMEM);
        cudaFuncSetAttribute(attn_kernel,   cudaFuncAttributeMaxDynamicSharedMemorySize, ATTN_SMEM);
        init = true;
    }

    prep_kernel<<<PREP_BLOCKS, 256>>>(qpos, W1, W2, Wq, Wk, Wv, Wo, bq, bv);
    gemm_qkv_mlp1<<<1024, 256, TSMEM>>>(query, b1);
    gemm_mlp2<<<256, 256, TSMEM>>>(b2);
    attn_kernel<<<dim3(16, HH), 256, ATTN_SMEM>>>();
    gemm_out<<<256, 256, TSMEM>>>(bo, query, out);
}

// round 10
// speedup vs baseline: 1.4556x; 1.4556x over previous
#include <cuda_runtime.h>
#include <math.h>
#include <stdint.h>

// Problem constants
#define BB    64
#define CC    512
#define HH    8
#define HD    64
#define FREQE 256
#define ROWS  4096   // B*N == N*M
#define WSLOT (CC * CC)

// ---------------------------------------------------------------------------
// Scratch (device globals; no allocation allowed)
// ---------------------------------------------------------------------------
__device__ float g_pe [ROWS * CC];
__device__ float g_q  [ROWS * CC];
__device__ float g_k  [ROWS * CC];
__device__ float g_v  [ROWS * CC];
__device__ float g_x  [ROWS * CC];
__device__ float g_emb[ROWS * FREQE];
__device__ float g_hid[ROWS * CC];
__device__ float g_bqkv[3 * CC];
__device__ float g_wt [6 * CC * CC];    // transposed W1,W2,Wq,Wk,Wv,Wo (fp32)

__device__ __forceinline__ uint32_t to_tf32(float x) {
    uint32_t u;
    asm("cvt.rna.tf32.f32 %0, %1;" : "=r"(u) : "f"(x));
    return u;
}

__device__ __forceinline__ uint32_t smem_u32(const void* p) {
    uint32_t a;
    asm("{ .reg .u64 t; cvta.to.shared.u64 t, %1; cvt.u32.u64 %0, t; }"
        : "=r"(a) : "l"(p));
    return a;
}

__device__ __forceinline__ void cp16(uint32_t dst, const void* src) {
    asm volatile("cp.async.cg.shared.global [%0], [%1], 16;" :: "r"(dst), "l"(src));
}
#define CP_COMMIT() asm volatile("cp.async.commit_group;" ::: "memory")
#define CP_WAIT(n)  asm volatile("cp.async.wait_group %0;" :: "n"(n) : "memory")

// ---------------------------------------------------------------------------
// Node 1 — prep: embedding + 6 weight transposes + fused qkv bias.
// ---------------------------------------------------------------------------
#define PREP_BLOCKS (4096 + 1536 + 6)

__global__ __launch_bounds__(256) void prep_kernel(
    const float* __restrict__ qpos,
    const float* __restrict__ W1, const float* __restrict__ W2,
    const float* __restrict__ Wq, const float* __restrict__ Wk,
    const float* __restrict__ Wv, const float* __restrict__ Wo,
    const float* __restrict__ bq, const float* __restrict__ bv)
{
    int bid = blockIdx.x;
    int t = threadIdx.x;

    if (bid < 4096) {                       // embedding
        int idx = bid * 256 + t;
        int p = idx >> 8;
        int j = idx & 255;
        float tp = qpos[p];
        int jj = j & 127;
        float f = expf(-9.210340371976184f * (float)jj * (1.0f / 128.0f));
        float a = tp * f;
        g_emb[idx] = (j < 128) ? cosf(a) : sinf(a);
        return;
    }
    if (bid < 5632) {                       // weight transposes
        int bid2 = bid - 4096;
        int slot = bid2 >> 8;               // 0..5
        int r    = bid2 & 255;
        int k0 = (r & 15) * 32;
        int n0 = (r >> 4) * 32;
        int K = (slot == 0) ? FREQE : CC;
        if (k0 >= K) return;

        const float* W = (slot == 0) ? W1 : (slot == 1) ? W2 : (slot == 2) ? Wq
                       : (slot == 3) ? Wk : (slot == 4) ? Wv : Wo;

        __shared__ float sm[32][33];
        int tx = t & 31, ty = t >> 5;
#pragma unroll
        for (int i = 0; i < 4; i++) {
            int rr = ty + i * 8;
            sm[rr][tx] = W[(size_t)(k0 + rr) * CC + n0 + tx];
        }
        __syncthreads();
#pragma unroll
        for (int i = 0; i < 4; i++) {
            int rr = ty + i * 8;
            g_wt[(size_t)slot * WSLOT + (size_t)(n0 + rr) * K + k0 + tx] = sm[tx][rr];
        }
        return;
    }
    {                                       // bias fuse
        int i = (bid - 5632) * 256 + t;
        float v = 0.0f;
        if (i < 512) v = bq[i];
        else if (i >= 1024) v = bv[i - 1024];
        g_bqkv[i] = v;
    }
}

// ---------------------------------------------------------------------------
// 1xTF32 GEMM body (unchanged, proven at plateau)
// ---------------------------------------------------------------------------
#define TPAD 36
#define ATILE (64 * TPAD * 4)
#define BTILE (128 * TPAD * 4)
#define TSMEM (2 * ATILE + 2 * BTILE)   // 55296 B

#define MMA1688T(d, a, b) \
    asm volatile( \
        "mma.sync.aligned.m16n8k8.row.col.f32.tf32.tf32.f32 " \
        "{%0,%1,%2,%3}, {%4,%5,%6,%7}, {%8,%9}, {%0,%1,%2,%3};" \
        : "+f"((d)[0]), "+f"((d)[1]), "+f"((d)[2]), "+f"((d)[3]) \
        : "r"((a)[0]), "r"((a)[1]), "r"((a)[2]), "r"((a)[3]), \
          "r"((b)[0]), "r"((b)[1]))

__device__ __forceinline__ void gemm_body(
    const float* __restrict__ A, const float* __restrict__ Bt,
    const float* __restrict__ bias, const float* __restrict__ resid,
    float* __restrict__ Cf, float* __restrict__ C2, float* __restrict__ C3,
    int K, int epi, int bx, int by, float* smf)
{
    uint32_t sbase = smem_u32(smf);
    int t = threadIdx.x, lane = t & 31, wid = t >> 5;
    int wm = wid >> 2;
    int wn = wid & 3;
    int m0 = by * 64, n0 = bx * 128;
    int gr = lane >> 2, gc = lane & 3;

    float acc[2][4][4];
#pragma unroll
    for (int mi = 0; mi < 2; mi++)
#pragma unroll
        for (int ni = 0; ni < 4; ni++)
#pragma unroll
            for (int j = 0; j < 4; j++) acc[mi][ni][j] = 0.0f;

    int nch = K >> 5;

    auto load_chunk = [&](int ch, int buf) {
        int k0 = ch << 5;
#pragma unroll
        for (int i = 0; i < 2; i++) {
            int idx = t + i * 256;
            int row = idx >> 3;
            int c   = idx & 7;
            uint32_t off = (uint32_t)(row * TPAD * 4 + c * 16);
            cp16(sbase + buf * ATILE + off,
                 A + (size_t)(m0 + row) * K + k0 + c * 4);
        }
#pragma unroll
        for (int i = 0; i < 4; i++) {
            int idx = t + i * 256;
            int row = idx >> 3;
            int c   = idx & 7;
            uint32_t off = (uint32_t)(row * TPAD * 4 + c * 16);
            cp16(sbase + 2 * ATILE + buf * BTILE + off,
                 Bt + (size_t)(n0 + row) * K + k0 + c * 4);
        }
        CP_COMMIT();
    };

    load_chunk(0, 0);
    load_chunk(1, 1);

    for (int ch = 0; ch < nch; ch++) {
        if (ch + 1 < nch) { CP_WAIT(1); } else { CP_WAIT(0); }
        __syncthreads();

        int buf = ch & 1;
        const float* sA = smf + (buf * ATILE >> 2);
        const float* sB = smf + ((2 * ATILE + buf * BTILE) >> 2);

#pragma unroll
        for (int ks = 0; ks < 4; ks++) {
            int kk = ks * 8;
            uint32_t af[2][4], bf[4][2];
#pragma unroll
            for (int mi = 0; mi < 2; mi++) {
                int base = (wm * 32 + mi * 16 + gr) * TPAD + kk;
                af[mi][0] = to_tf32(sA[base + gc]);
                af[mi][1] = to_tf32(sA[base + 8 * TPAD + gc]);
                af[mi][2] = to_tf32(sA[base + gc + 4]);
                af[mi][3] = to_tf32(sA[base + 8 * TPAD + gc + 4]);
            }
#pragma unroll
            for (int ni = 0; ni < 4; ni++) {
                int base = (wn * 32 + ni * 8 + gr) * TPAD + kk;
                bf[ni][0] = to_tf32(sB[base + gc]);
                bf[ni][1] = to_tf32(sB[base + gc + 4]);
            }
#pragma unroll
            for (int mi = 0; mi < 2; mi++)
#pragma unroll
                for (int ni = 0; ni < 4; ni++)
                    MMA1688T(acc[mi][ni], af[mi], bf[ni]);
        }
        __syncthreads();
        if (ch + 2 < nch) load_chunk(ch + 2, buf);
    }

#pragma unroll
    for (int mi = 0; mi < 2; mi++) {
#pragma unroll
        for (int ni = 0; ni < 4; ni++) {
            int row0 = m0 + wm * 32 + mi * 16 + gr;
            int col  = n0 + wn * 32 + ni * 8 + gc * 2;
#pragma unroll
            for (int half = 0; half < 2; half++) {
                int row = row0 + half * 8;
                float v0 = acc[mi][ni][half * 2 + 0];
                float v1 = acc[mi][ni][half * 2 + 1];
                if (bias) { v0 += bias[col]; v1 += bias[col + 1]; }
                if (epi == 1) {
                    v0 = v0 / (1.0f + expf(-v0));
                    v1 = v1 / (1.0f + expf(-v1));
                }
                if (epi == 3) {
                    int seg = col >> 9;
                    float* dst = (seg == 0) ? Cf : (seg == 1) ? C2 : C3;
                    size_t o = (size_t)row * CC + (col & 511);
                    *(float2*)(dst + o) = make_float2(v0, v1);
                } else {
                    size_t o = (size_t)row * CC + col;
                    if (epi == 2) {
                        v0 += resid[o];
                        v1 += resid[o + 1];
                    }
                    *(float2*)(Cf + o) = make_float2(v0, v1);
                }
            }
        }
    }
}

// Node 2 — QKV (768 blocks) + MLP1 (256 blocks) fused
__global__ __launch_bounds__(256, 2) void gemm_qkv_mlp1(
    const float* __restrict__ query, const float* __restrict__ b1)
{
    extern __shared__ float smf[];
    int bid = blockIdx.x;
    if (bid < 768) {
        gemm_body(query, g_wt + 2 * WSLOT, g_bqkv, nullptr,
                  g_q, g_k, g_v, CC, 3, bid % 12, bid / 12, smf);
    } else {
        int b2 = bid - 768;
        gemm_body(g_emb, g_wt + 0 * WSLOT, b1, nullptr,
                  g_hid, nullptr, nullptr, FREQE, 1, b2 & 3, b2 >> 2, smf);
    }
}

// Node 3 — MLP2
__global__ __launch_bounds__(256, 2) void gemm_mlp2(const float* __restrict__ b2)
{
    extern __shared__ float smf[];
    int bid = blockIdx.x;
    gemm_body(g_hid, g_wt + 1 * WSLOT, b2, nullptr,
              g_pe, nullptr, nullptr, CC, 0, bid & 3, bid >> 2, smf);
}

// Node 5 — output projection + bias + residual
__global__ __launch_bounds__(256, 2) void gemm_out(
    const float* __restrict__ bo, const float* __restrict__ query,
    float* __restrict__ out)
{
    extern __shared__ float smf[];
    int bid = blockIdx.x;
    gemm_body(g_x, g_wt + 5 * WSLOT, bo, query,
              out, nullptr, nullptr, CC, 2, bid & 3, bid >> 2, smf);
}

// ---------------------------------------------------------------------------
// Node 4 — attention, cp.async-pipelined pe streaming.
// Block = (2 batches, 1 head); grid (32, 8) = 256 blocks; 2 CTAs/SM.
// K, V register-resident (32 each); pe + q double-buffered in smem.
// PROW = 68 floats per padded row (272B, 16B-aligned).
// ---------------------------------------------------------------------------
#define PROW 68

__global__ __launch_bounds__(256, 2) void attn_kernel() {
    __shared__ float pe_sm[2][64 * PROW];   // 2 x 17408 B
    __shared__ float q_sm[2][2][64];
    __shared__ float s[2][64];

    int h   = blockIdx.y;
    int b0  = blockIdx.x * 2;
    int t   = threadIdx.x;

    uint32_t pe_base0 = smem_u32(&pe_sm[0][0]);
    uint32_t pe_base1 = smem_u32(&pe_sm[1][0]);
    uint32_t q_base   = smem_u32(&q_sm[0][0][0]);

    // scores decode: b, m, dg(2 halves of d)
    int sb = t >> 7, srem = t & 127, sm_ = srem >> 1, sdg = srem & 1;
    // AV decode: b, d, mg(2 halves of m)
    int ab = t >> 7, arem = t & 127, ad = arem >> 1, amg = arem & 1;

    // ---- stage K tiles (b=0 -> buf0, b=1 -> buf1), pull into kreg ----
#pragma unroll
    for (int i = 0; i < 8; i++) {
        int c = t + i * 256;                // 0..2047
        int b = c >> 10;
        int r = (c >> 4) & 63;
        int j = c & 15;
        uint32_t dst = (b == 0 ? pe_base0 : pe_base1) + (uint32_t)(r * PROW * 4 + j * 16);
        cp16(dst, g_k + ((size_t)((b0 + b) * 64 + r)) * 512 + h * 64 + j * 4);
    }
    CP_COMMIT(); CP_WAIT(0);
    __syncthreads();

    float kreg[32];
    {
        const float* src = &pe_sm[sb][sm_ * PROW + sdg * 32];
#pragma unroll
        for (int j4 = 0; j4 < 8; j4++) {
            float4 v = *(const float4*)(src + j4 * 4);
            kreg[j4 * 4 + 0] = v.x; kreg[j4 * 4 + 1] = v.y;
            kreg[j4 * 4 + 2] = v.z; kreg[j4 * 4 + 3] = v.w;
        }
    }
    __syncthreads();

    // ---- stage V tiles, pull into vreg (column d, half mg) ----
#pragma unroll
    for (int i = 0; i < 8; i++) {
        int c = t + i * 256;
        int b = c >> 10;
        int r = (c >> 4) & 63;
        int j = c & 15;
        uint32_t dst = (b == 0 ? pe_base0 : pe_base1) + (uint32_t)(r * PROW * 4 + j * 16);
        cp16(dst, g_v + ((size_t)((b0 + b) * 64 + r)) * 512 + h * 64 + j * 4);
    }
    CP_COMMIT(); CP_WAIT(0);
    __syncthreads();

    float vreg[32];
    {
        const float* src = &pe_sm[ab][0];
#pragma unroll
        for (int j = 0; j < 32; j++)
            vreg[j] = src[(amg * 32 + j) * PROW + ad];
    }
    __syncthreads();

    // ---- pipeline: stage pe[n] (1024 chunks) + q[n] (32 chunks) ----
    auto stage = [&](int n) {
        int buf = n & 1;
        uint32_t pb = buf ? pe_base1 : pe_base0;
#pragma unroll
        for (int i = 0; i < 4; i++) {
            int c = t + i * 256;            // 0..1023
            int m = c >> 4;
            int j = c & 15;
            cp16(pb + (uint32_t)(m * PROW * 4 + j * 16),
                 g_pe + ((size_t)(n * 64 + m)) * 512 + h * 64 + j * 4);
        }
        if (t < 32) {
            int b = t >> 4, j = t & 15;
            cp16(q_base + (uint32_t)(((buf * 2 + b) * 64 + j * 4) * 4),
                 g_q + ((size_t)((b0 + b) * 64 + n)) * 512 + h * 64 + j * 4);
        }
        CP_COMMIT();
    };

    stage(0);

    for (int n = 0; n < 64; n++) {
        if (n + 1 < 64) { stage(n + 1); CP_WAIT(1); } else { CP_WAIT(0); }
        __syncthreads();   // pe[n], q[n] visible; also guards s (AV(n-1) done)

        int buf = n & 1;

        // scores: thread (sb, sm_, sdg)
        {
            const float* pep = &pe_sm[buf][sm_ * PROW + sdg * 32];
            const float* qp  = &q_sm[buf][sb][sdg * 32];
            float p = 0.0f;
#pragma unroll
            for (int j4 = 0; j4 < 8; j4++) {
                float4 pe4 = *(const float4*)(pep + j4 * 4);
                float4 q4  = *(const float4*)(qp + j4 * 4);
                p = fmaf(q4.x * kreg[j4 * 4 + 0], pe4.x, p);
                p = fmaf(q4.y * kreg[j4 * 4 + 1], pe4.y, p);
                p = fmaf(q4.z * kreg[j4 * 4 + 2], pe4.z, p);
                p = fmaf(q4.w * kreg[j4 * 4 + 3], pe4.w, p);
            }
            p += __shfl_xor_sync(0xffffffffu, p, 1);
            if (sdg == 0) s[sb][sm_] = p * 0.125f;
        }
        __syncthreads();

        // softmax: warp 0 -> b0, warp 1 -> b1
        if (t < 64) {
            int w = t >> 5, lane = t & 31;
            float a  = s[w][lane];
            float c2 = s[w][lane + 32];
            float mx = fmaxf(a, c2);
#pragma unroll
            for (int off = 16; off > 0; off >>= 1)
                mx = fmaxf(mx, __shfl_xor_sync(0xffffffffu, mx, off));
            float e1 = __expf(a - mx), e2 = __expf(c2 - mx);
            float smv = e1 + e2;
#pragma unroll
            for (int off = 16; off > 0; off >>= 1)
                smv += __shfl_xor_sync(0xffffffffu, smv, off);
            float inv = 1.0f / smv;
            s[w][lane]      = e1 * inv;
            s[w][lane + 32] = e2 * inv;
        }
        __syncthreads();

        // AV: thread (ab, ad, amg)
        {
            float xv = 0.0f;
            const float* sp = &s[ab][amg * 32];
#pragma unroll
            for (int j = 0; j < 32; j++)
                xv = fmaf(sp[j], vreg[j], xv);
            xv += __shfl_xor_sync(0xffffffffu, xv, 1);
            if (amg == 0)
                g_x[((size_t)((b0 + ab) * 64 + n)) * 512 + h * 64 + ad] = xv;
        }
        // next iteration's post-wait barrier guards s/pe reuse
    }
}

// ---------------------------------------------------------------------------
// Launch — 5 nodes, single stream.
// ---------------------------------------------------------------------------
extern "C" void kernel_launch(void* const* d_in, const int* in_sizes, int n_in,
                              void* d_out, int out_size)
{
    const float* query = (const float*)d_in[0];
    const float* qpos  = (const float*)d_in[1];
    const float* Wq    = (const float*)d_in[2];
    const float* bq    = (const float*)d_in[3];
    const float* Wk    = (const float*)d_in[4];
    const float* Wv    = (const float*)d_in[5];
    const float* bv    = (const float*)d_in[6];
    const float* Wo    = (const float*)d_in[7];
    const float* bo    = (const float*)d_in[8];
    const float* W1    = (const float*)d_in[9];
    const float* b1    = (const float*)d_in[10];
    const float* W2    = (const float*)d_in[11];
    const float* b2    = (const float*)d_in[12];
    float* out = (float*)d_out;

    static bool init = false;
    if (!init) {
        cudaFuncSetAttribute(gemm_qkv_mlp1, cudaFuncAttributeMaxDynamicSharedMemorySize, TSMEM);
        cudaFuncSetAttribute(gemm_mlp2,     cudaFuncAttributeMaxDynamicSharedMemorySize, TSMEM);
        cudaFuncSetAttribute(gemm_out,      cudaFuncAttributeMaxDynamicSharedMemorySize, TSMEM);
        init = true;
    }

    prep_kernel<<<PREP_BLOCKS, 256>>>(qpos, W1, W2, Wq, Wk, Wv, Wo, bq, bv);
    gemm_qkv_mlp1<<<1024, 256, TSMEM>>>(query, b1);
    gemm_mlp2<<<256, 256, TSMEM>>>(b2);
    attn_kernel<<<dim3(32, HH), 256>>>();
    gemm_out<<<256, 256, TSMEM>>>(bo, query, out);
}

// round 11
// speedup vs baseline: 1.5381x; 1.0567x over previous
#include <cuda_runtime.h>
#include <math.h>
#include <stdint.h>

// Problem constants
#define BB    64
#define CC    512
#define HH    8
#define HD    64
#define FREQE 256
#define ROWS  4096   // B*N == N*M
#define WSLOT (CC * CC)

// ---------------------------------------------------------------------------
// Scratch (device globals; no allocation allowed)
// ---------------------------------------------------------------------------
__device__ float g_pe [ROWS * CC];
__device__ float g_q  [ROWS * CC];
__device__ float g_k  [ROWS * CC];
__device__ float g_v  [ROWS * CC];
__device__ float g_x  [ROWS * CC];
__device__ float g_emb[ROWS * FREQE];
__device__ float g_hid[ROWS * CC];
__device__ float g_bqkv[3 * CC];
__device__ float g_wt [6 * CC * CC];    // transposed W1,W2,Wq,Wk,Wv,Wo (fp32)

__device__ __forceinline__ uint32_t to_tf32(float x) {
    uint32_t u;
    asm("cvt.rna.tf32.f32 %0, %1;" : "=r"(u) : "f"(x));
    return u;
}

__device__ __forceinline__ uint32_t smem_u32(const void* p) {
    uint32_t a;
    asm("{ .reg .u64 t; cvta.to.shared.u64 t, %1; cvt.u32.u64 %0, t; }"
        : "=r"(a) : "l"(p));
    return a;
}

__device__ __forceinline__ void cp16(uint32_t dst, const void* src) {
    asm volatile("cp.async.cg.shared.global [%0], [%1], 16;" :: "r"(dst), "l"(src));
}
#define CP_COMMIT() asm volatile("cp.async.commit_group;" ::: "memory")
#define CP_WAIT(n)  asm volatile("cp.async.wait_group %0;" :: "n"(n) : "memory")

// ---------------------------------------------------------------------------
// Node 1 — prep: embedding + 6 weight transposes + fused qkv bias.
// ---------------------------------------------------------------------------
#define PREP_BLOCKS (4096 + 1536 + 6)

__global__ __launch_bounds__(256) void prep_kernel(
    const float* __restrict__ qpos,
    const float* __restrict__ W1, const float* __restrict__ W2,
    const float* __restrict__ Wq, const float* __restrict__ Wk,
    const float* __restrict__ Wv, const float* __restrict__ Wo,
    const float* __restrict__ bq, const float* __restrict__ bv)
{
    int bid = blockIdx.x;
    int t = threadIdx.x;

    if (bid < 4096) {                       // embedding
        int idx = bid * 256 + t;
        int p = idx >> 8;
        int j = idx & 255;
        float tp = qpos[p];
        int jj = j & 127;
        float f = expf(-9.210340371976184f * (float)jj * (1.0f / 128.0f));
        float a = tp * f;
        g_emb[idx] = (j < 128) ? cosf(a) : sinf(a);
        return;
    }
    if (bid < 5632) {                       // weight transposes
        int bid2 = bid - 4096;
        int slot = bid2 >> 8;               // 0..5
        int r    = bid2 & 255;
        int k0 = (r & 15) * 32;
        int n0 = (r >> 4) * 32;
        int K = (slot == 0) ? FREQE : CC;
        if (k0 >= K) return;

        const float* W = (slot == 0) ? W1 : (slot == 1) ? W2 : (slot == 2) ? Wq
                       : (slot == 3) ? Wk : (slot == 4) ? Wv : Wo;

        __shared__ float sm[32][33];
        int tx = t & 31, ty = t >> 5;
#pragma unroll
        for (int i = 0; i < 4; i++) {
            int rr = ty + i * 8;
            sm[rr][tx] = W[(size_t)(k0 + rr) * CC + n0 + tx];
        }
        __syncthreads();
#pragma unroll
        for (int i = 0; i < 4; i++) {
            int rr = ty + i * 8;
            g_wt[(size_t)slot * WSLOT + (size_t)(n0 + rr) * K + k0 + tx] = sm[tx][rr];
        }
        return;
    }
    {                                       // bias fuse
        int i = (bid - 5632) * 256 + t;
        float v = 0.0f;
        if (i < 512) v = bq[i];
        else if (i >= 1024) v = bv[i - 1024];
        g_bqkv[i] = v;
    }
}

// ---------------------------------------------------------------------------
// 1xTF32 GEMM body (unchanged, proven at plateau)
// ---------------------------------------------------------------------------
#define TPAD 36
#define ATILE (64 * TPAD * 4)
#define BTILE (128 * TPAD * 4)
#define TSMEM (2 * ATILE + 2 * BTILE)   // 55296 B

#define MMA1688T(d, a, b) \
    asm volatile( \
        "mma.sync.aligned.m16n8k8.row.col.f32.tf32.tf32.f32 " \
        "{%0,%1,%2,%3}, {%4,%5,%6,%7}, {%8,%9}, {%0,%1,%2,%3};" \
        : "+f"((d)[0]), "+f"((d)[1]), "+f"((d)[2]), "+f"((d)[3]) \
        : "r"((a)[0]), "r"((a)[1]), "r"((a)[2]), "r"((a)[3]), \
          "r"((b)[0]), "r"((b)[1]))

__device__ __forceinline__ void gemm_body(
    const float* __restrict__ A, const float* __restrict__ Bt,
    const float* __restrict__ bias, const float* __restrict__ resid,
    float* __restrict__ Cf, float* __restrict__ C2, float* __restrict__ C3,
    int K, int epi, int bx, int by, float* smf)
{
    uint32_t sbase = smem_u32(smf);
    int t = threadIdx.x, lane = t & 31, wid = t >> 5;
    int wm = wid >> 2;
    int wn = wid & 3;
    int m0 = by * 64, n0 = bx * 128;
    int gr = lane >> 2, gc = lane & 3;

    float acc[2][4][4];
#pragma unroll
    for (int mi = 0; mi < 2; mi++)
#pragma unroll
        for (int ni = 0; ni < 4; ni++)
#pragma unroll
            for (int j = 0; j < 4; j++) acc[mi][ni][j] = 0.0f;

    int nch = K >> 5;

    auto load_chunk = [&](int ch, int buf) {
        int k0 = ch << 5;
#pragma unroll
        for (int i = 0; i < 2; i++) {
            int idx = t + i * 256;
            int row = idx >> 3;
            int c   = idx & 7;
            uint32_t off = (uint32_t)(row * TPAD * 4 + c * 16);
            cp16(sbase + buf * ATILE + off,
                 A + (size_t)(m0 + row) * K + k0 + c * 4);
        }
#pragma unroll
        for (int i = 0; i < 4; i++) {
            int idx = t + i * 256;
            int row = idx >> 3;
            int c   = idx & 7;
            uint32_t off = (uint32_t)(row * TPAD * 4 + c * 16);
            cp16(sbase + 2 * ATILE + buf * BTILE + off,
                 Bt + (size_t)(n0 + row) * K + k0 + c * 4);
        }
        CP_COMMIT();
    };

    load_chunk(0, 0);
    load_chunk(1, 1);

    for (int ch = 0; ch < nch; ch++) {
        if (ch + 1 < nch) { CP_WAIT(1); } else { CP_WAIT(0); }
        __syncthreads();

        int buf = ch & 1;
        const float* sA = smf + (buf * ATILE >> 2);
        const float* sB = smf + ((2 * ATILE + buf * BTILE) >> 2);

#pragma unroll
        for (int ks = 0; ks < 4; ks++) {
            int kk = ks * 8;
            uint32_t af[2][4], bf[4][2];
#pragma unroll
            for (int mi = 0; mi < 2; mi++) {
                int base = (wm * 32 + mi * 16 + gr) * TPAD + kk;
                af[mi][0] = to_tf32(sA[base + gc]);
                af[mi][1] = to_tf32(sA[base + 8 * TPAD + gc]);
                af[mi][2] = to_tf32(sA[base + gc + 4]);
                af[mi][3] = to_tf32(sA[base + 8 * TPAD + gc + 4]);
            }
#pragma unroll
            for (int ni = 0; ni < 4; ni++) {
                int base = (wn * 32 + ni * 8 + gr) * TPAD + kk;
                bf[ni][0] = to_tf32(sB[base + gc]);
                bf[ni][1] = to_tf32(sB[base + gc + 4]);
            }
#pragma unroll
            for (int mi = 0; mi < 2; mi++)
#pragma unroll
                for (int ni = 0; ni < 4; ni++)
                    MMA1688T(acc[mi][ni], af[mi], bf[ni]);
        }
        __syncthreads();
        if (ch + 2 < nch) load_chunk(ch + 2, buf);
    }

#pragma unroll
    for (int mi = 0; mi < 2; mi++) {
#pragma unroll
        for (int ni = 0; ni < 4; ni++) {
            int row0 = m0 + wm * 32 + mi * 16 + gr;
            int col  = n0 + wn * 32 + ni * 8 + gc * 2;
#pragma unroll
            for (int half = 0; half < 2; half++) {
                int row = row0 + half * 8;
                float v0 = acc[mi][ni][half * 2 + 0];
                float v1 = acc[mi][ni][half * 2 + 1];
                if (bias) { v0 += bias[col]; v1 += bias[col + 1]; }
                if (epi == 1) {
                    v0 = v0 / (1.0f + expf(-v0));
                    v1 = v1 / (1.0f + expf(-v1));
                }
                if (epi == 3) {
                    int seg = col >> 9;
                    float* dst = (seg == 0) ? Cf : (seg == 1) ? C2 : C3;
                    size_t o = (size_t)row * CC + (col & 511);
                    *(float2*)(dst + o) = make_float2(v0, v1);
                } else {
                    size_t o = (size_t)row * CC + col;
                    if (epi == 2) {
                        v0 += resid[o];
                        v1 += resid[o + 1];
                    }
                    *(float2*)(Cf + o) = make_float2(v0, v1);
                }
            }
        }
    }
}

// Node 2 — QKV (768 blocks) + MLP1 (256 blocks) fused
__global__ __launch_bounds__(256, 2) void gemm_qkv_mlp1(
    const float* __restrict__ query, const float* __restrict__ b1)
{
    extern __shared__ float smf[];
    int bid = blockIdx.x;
    if (bid < 768) {
        gemm_body(query, g_wt + 2 * WSLOT, g_bqkv, nullptr,
                  g_q, g_k, g_v, CC, 3, bid % 12, bid / 12, smf);
    } else {
        int b2 = bid - 768;
        gemm_body(g_emb, g_wt + 0 * WSLOT, b1, nullptr,
                  g_hid, nullptr, nullptr, FREQE, 1, b2 & 3, b2 >> 2, smf);
    }
}

// Node 3 — MLP2
__global__ __launch_bounds__(256, 2) void gemm_mlp2(const float* __restrict__ b2)
{
    extern __shared__ float smf[];
    int bid = blockIdx.x;
    gemm_body(g_hid, g_wt + 1 * WSLOT, b2, nullptr,
              g_pe, nullptr, nullptr, CC, 0, bid & 3, bid >> 2, smf);
}

// Node 5 — output projection + bias + residual
__global__ __launch_bounds__(256, 2) void gemm_out(
    const float* __restrict__ bo, const float* __restrict__ query,
    float* __restrict__ out)
{
    extern __shared__ float smf[];
    int bid = blockIdx.x;
    gemm_body(g_x, g_wt + 5 * WSLOT, bo, query,
              out, nullptr, nullptr, CC, 2, bid & 3, bid >> 2, smf);
}

// ---------------------------------------------------------------------------
// Node 4 — phase-structured attention.
// Block = (2 batches, head); grid (32, 8); 256 threads; 2 CTAs/SM.
// smem layout (floats): pe[2][T] | q[2][T] | s[2][T], T = 64*PROW.
// Phase 1: scores for all n (pipelined pe); Phase 2: parallel softmax;
// Phase 3: AV with register-resident V (loaded into freed pe buffers).
// ---------------------------------------------------------------------------
#define PROW 68
#define TFL  (64 * PROW)                 // floats per tile
#define ATTN_SMEM2 (6 * TFL * 4)         // 104448 B

__global__ __launch_bounds__(256, 2) void attn_kernel() {
    extern __shared__ float smf[];
    float* pe_sm = smf;                  // [2][TFL]
    float* q_sm  = smf + 2 * TFL;        // [2][TFL]
    float* s_sm  = smf + 4 * TFL;        // [2][TFL]

    uint32_t pe_u = smem_u32(pe_sm);
    uint32_t q_u  = smem_u32(q_sm);

    int h  = blockIdx.y;
    int b0 = blockIdx.x * 2;
    int t  = threadIdx.x;

    // ---- G1: stage K (both b) into pe buffers + Q (both b) into q_sm ----
#pragma unroll
    for (int i = 0; i < 8; i++) {
        int c = t + i * 256;             // 0..2047
        int b = c >> 10;
        int r = (c >> 4) & 63;
        int j = c & 15;
        const float* srcK = g_k + ((size_t)((b0 + b) * 64 + r)) * 512 + h * 64 + j * 4;
        const float* srcQ = g_q + ((size_t)((b0 + b) * 64 + r)) * 512 + h * 64 + j * 4;
        uint32_t off = (uint32_t)((b * TFL + r * PROW) * 4 + j * 16);
        cp16(pe_u + off, srcK);
        cp16(q_u  + off, srcQ);
    }
    CP_COMMIT();
    CP_WAIT(0);
    __syncthreads();

    // ---- pull K into registers: thread (m = t>>2, dq = t&3) covers both b ----
    int m  = t >> 2;
    int dq = t & 3;
    float4 kreg[2][4];
#pragma unroll
    for (int b = 0; b < 2; b++)
#pragma unroll
        for (int c = 0; c < 4; c++)
            kreg[b][c] = *(const float4*)&pe_sm[b * TFL + m * PROW + 4 * dq + 16 * c];
    __syncthreads();   // kreg pulled before pe buffers are overwritten

    // ---- stage pe[0], pe[1] ----
    auto stage_pe = [&](int n) {
        int buf = n & 1;
#pragma unroll
        for (int i = 0; i < 4; i++) {
            int c = t + i * 256;         // 0..1023
            int r = c >> 4;
            int j = c & 15;
            cp16(pe_u + (uint32_t)((buf * TFL + r * PROW) * 4 + j * 16),
                 g_pe + ((size_t)(n * 64 + r)) * 512 + h * 64 + j * 4);
        }
        CP_COMMIT();
    };
    stage_pe(0);
    stage_pe(1);

    // ---- Phase 1: scores loop ----
    for (int n = 0; n < 64; n++) {
        if (n < 62) { CP_WAIT(1); } else { CP_WAIT(0); }
        __syncthreads();

        int buf = n & 1;
        float p0 = 0.0f, p1 = 0.0f;
        const float* peb = &pe_sm[buf * TFL + m * PROW + 4 * dq];
        const float* qb0 = &q_sm[0 * TFL + n * PROW + 4 * dq];
        const float* qb1 = &q_sm[1 * TFL + n * PROW + 4 * dq];
#pragma unroll
        for (int c = 0; c < 4; c++) {
            float4 pe4 = *(const float4*)(peb + 16 * c);
            float4 q0  = *(const float4*)(qb0 + 16 * c);
            float4 q1  = *(const float4*)(qb1 + 16 * c);
            p0 = fmaf(q0.x * kreg[0][c].x, pe4.x, p0);
            p0 = fmaf(q0.y * kreg[0][c].y, pe4.y, p0);
            p0 = fmaf(q0.z * kreg[0][c].z, pe4.z, p0);
            p0 = fmaf(q0.w * kreg[0][c].w, pe4.w, p0);
            p1 = fmaf(q1.x * kreg[1][c].x, pe4.x, p1);
            p1 = fmaf(q1.y * kreg[1][c].y, pe4.y, p1);
            p1 = fmaf(q1.z * kreg[1][c].z, pe4.z, p1);
            p1 = fmaf(q1.w * kreg[1][c].w, pe4.w, p1);
        }
        p0 += __shfl_xor_sync(0xffffffffu, p0, 1);
        p0 += __shfl_xor_sync(0xffffffffu, p0, 2);
        p1 += __shfl_xor_sync(0xffffffffu, p1, 1);
        p1 += __shfl_xor_sync(0xffffffffu, p1, 2);
        if (dq == 0) {
            s_sm[0 * TFL + n * PROW + m] = p0 * 0.125f;
            s_sm[1 * TFL + n * PROW + m] = p1 * 0.125f;
        }
        __syncthreads();
        if (n + 2 < 64) stage_pe(n + 2);
    }

    // ---- stage V into freed pe buffers (overlaps with softmax) ----
#pragma unroll
    for (int i = 0; i < 8; i++) {
        int c = t + i * 256;
        int b = c >> 10;
        int r = (c >> 4) & 63;
        int j = c & 15;
        cp16(pe_u + (uint32_t)((b * TFL + r * PROW) * 4 + j * 16),
             g_v + ((size_t)((b0 + b) * 64 + r)) * 512 + h * 64 + j * 4);
    }
    CP_COMMIT();

    // ---- Phase 2: softmax, thread (b, n, half) owns 32 entries ----
    {
        int b  = t >> 7;
        int n  = (t >> 1) & 63;
        int hf = t & 1;
        float* row = &s_sm[b * TFL + n * PROW + hf * 32];
        float4 e[8];
        float mx = -1e30f;
#pragma unroll
        for (int i = 0; i < 8; i++) {
            e[i] = *(const float4*)(row + i * 4);
            mx = fmaxf(mx, fmaxf(fmaxf(e[i].x, e[i].y), fmaxf(e[i].z, e[i].w)));
        }
        mx = fmaxf(mx, __shfl_xor_sync(0xffffffffu, mx, 1));
        float sum = 0.0f;
#pragma unroll
        for (int i = 0; i < 8; i++) {
            e[i].x = __expf(e[i].x - mx); e[i].y = __expf(e[i].y - mx);
            e[i].z = __expf(e[i].z - mx); e[i].w = __expf(e[i].w - mx);
            sum += e[i].x + e[i].y + e[i].z + e[i].w;
        }
        sum += __shfl_xor_sync(0xffffffffu, sum, 1);
        float inv = 1.0f / sum;
#pragma unroll
        for (int i = 0; i < 8; i++) {
            e[i].x *= inv; e[i].y *= inv; e[i].z *= inv; e[i].w *= inv;
            *(float4*)(row + i * 4) = e[i];
        }
    }

    CP_WAIT(0);
    __syncthreads();   // V staged + softmax stores visible

    // ---- Phase 3: AV. thread (d = t>>2, mg = t&3); V in registers ----
    {
        int d  = t >> 2;
        int mg = t & 3;
        float vreg[2][16];
#pragma unroll
        for (int b = 0; b < 2; b++)
#pragma unroll
            for (int j = 0; j < 16; j++)
                vreg[b][j] = pe_sm[b * TFL + (mg * 16 + j) * PROW + d];

        for (int n = 0; n < 64; n++) {
#pragma unroll
            for (int b = 0; b < 2; b++) {
                const float* sp = &s_sm[b * TFL + n * PROW + mg * 16];
                float acc = 0.0f;
#pragma unroll
                for (int c = 0; c < 4; c++) {
                    float4 s4 = *(const float4*)(sp + c * 4);
                    acc = fmaf(s4.x, vreg[b][c * 4 + 0], acc);
                    acc = fmaf(s4.y, vreg[b][c * 4 + 1], acc);
                    acc = fmaf(s4.z, vreg[b][c * 4 + 2], acc);
                    acc = fmaf(s4.w, vreg[b][c * 4 + 3], acc);
                }
                acc += __shfl_xor_sync(0xffffffffu, acc, 1);
                acc += __shfl_xor_sync(0xffffffffu, acc, 2);
                if (mg == 0)
                    g_x[((size_t)((b0 + b) * 64 + n)) * 512 + h * 64 + d] = acc;
            }
        }
    }
}

// ---------------------------------------------------------------------------
// Launch — 5 nodes, single stream.
// ---------------------------------------------------------------------------
extern "C" void kernel_launch(void* const* d_in, const int* in_sizes, int n_in,
                              void* d_out, int out_size)
{
    const float* query = (const float*)d_in[0];
    const float* qpos  = (const float*)d_in[1];
    const float* Wq    = (const float*)d_in[2];
    const float* bq    = (const float*)d_in[3];
    const float* Wk    = (const float*)d_in[4];
    const float* Wv    = (const float*)d_in[5];
    const float* bv    = (const float*)d_in[6];
    const float* Wo    = (const float*)d_in[7];
    const float* bo    = (const float*)d_in[8];
    const float* W1    = (const float*)d_in[9];
    const float* b1    = (const float*)d_in[10];
    const float* W2    = (const float*)d_in[11];
    const float* b2    = (const float*)d_in[12];
    float* out = (float*)d_out;

    static bool init = false;
    if (!init) {
        cudaFuncSetAttribute(gemm_qkv_mlp1, cudaFuncAttributeMaxDynamicSharedMemorySize, TSMEM);
        cudaFuncSetAttribute(gemm_mlp2,     cudaFuncAttributeMaxDynamicSharedMemorySize, TSMEM);
        cudaFuncSetAttribute(gemm_out,      cudaFuncAttributeMaxDynamicSharedMemorySize, TSMEM);
        cudaFuncSetAttribute(attn_kernel,   cudaFuncAttributeMaxDynamicSharedMemorySize, ATTN_SMEM2);
        init = true;
    }

    prep_kernel<<<PREP_BLOCKS, 256>>>(qpos, W1, W2, Wq, Wk, Wv, Wo, bq, bv);
    gemm_qkv_mlp1<<<1024, 256, TSMEM>>>(query, b1);
    gemm_mlp2<<<256, 256, TSMEM>>>(b2);
    attn_kernel<<<dim3(32, HH), 256, ATTN_SMEM2>>>();
    gemm_out<<<256, 256, TSMEM>>>(bo, query, out);
}

// round 12
// speedup vs baseline: 1.8885x; 1.2278x over previous
#include <cuda_runtime.h>
#include <math.h>
#include <stdint.h>

// Problem constants
#define BB    64
#define CC    512
#define HH    8
#define HD    64
#define FREQE 256
#define ROWS  4096   // B*N == N*M
#define WSLOT (CC * CC)

// ---------------------------------------------------------------------------
// Scratch (device globals; no allocation allowed)
// ---------------------------------------------------------------------------
__device__ float g_pe [ROWS * CC];
__device__ float g_q  [ROWS * CC];
__device__ float g_k  [ROWS * CC];
__device__ float g_v  [ROWS * CC];
__device__ float g_x  [ROWS * CC];
__device__ float g_emb[ROWS * FREQE];
__device__ float g_hid[ROWS * CC];
__device__ float g_bqkv[3 * CC];
__device__ float g_wt [6 * CC * CC];    // transposed W1,W2,Wq,Wk,Wv,Wo (fp32)

__device__ __forceinline__ uint32_t to_tf32(float x) {
    uint32_t u;
    asm("cvt.rna.tf32.f32 %0, %1;" : "=r"(u) : "f"(x));
    return u;
}

__device__ __forceinline__ uint32_t smem_u32(const void* p) {
    uint32_t a;
    asm("{ .reg .u64 t; cvta.to.shared.u64 t, %1; cvt.u32.u64 %0, t; }"
        : "=r"(a) : "l"(p));
    return a;
}

__device__ __forceinline__ void cp16(uint32_t dst, const void* src) {
    asm volatile("cp.async.cg.shared.global [%0], [%1], 16;" :: "r"(dst), "l"(src));
}
#define CP_COMMIT() asm volatile("cp.async.commit_group;" ::: "memory")
#define CP_WAIT(n)  asm volatile("cp.async.wait_group %0;" :: "n"(n) : "memory")

// ---------------------------------------------------------------------------
// Node 1 — prep: embedding + 6 weight transposes + fused qkv bias.
// ---------------------------------------------------------------------------
#define PREP_BLOCKS (4096 + 1536 + 6)

__global__ __launch_bounds__(256) void prep_kernel(
    const float* __restrict__ qpos,
    const float* __restrict__ W1, const float* __restrict__ W2,
    const float* __restrict__ Wq, const float* __restrict__ Wk,
    const float* __restrict__ Wv, const float* __restrict__ Wo,
    const float* __restrict__ bq, const float* __restrict__ bv)
{
    int bid = blockIdx.x;
    int t = threadIdx.x;

    if (bid < 4096) {                       // embedding
        int idx = bid * 256 + t;
        int p = idx >> 8;
        int j = idx & 255;
        float tp = qpos[p];
        int jj = j & 127;
        float f = expf(-9.210340371976184f * (float)jj * (1.0f / 128.0f));
        float a = tp * f;
        g_emb[idx] = (j < 128) ? cosf(a) : sinf(a);
        return;
    }
    if (bid < 5632) {                       // weight transposes
        int bid2 = bid - 4096;
        int slot = bid2 >> 8;               // 0..5
        int r    = bid2 & 255;
        int k0 = (r & 15) * 32;
        int n0 = (r >> 4) * 32;
        int K = (slot == 0) ? FREQE : CC;
        if (k0 >= K) return;

        const float* W = (slot == 0) ? W1 : (slot == 1) ? W2 : (slot == 2) ? Wq
                       : (slot == 3) ? Wk : (slot == 4) ? Wv : Wo;

        __shared__ float sm[32][33];
        int tx = t & 31, ty = t >> 5;
#pragma unroll
        for (int i = 0; i < 4; i++) {
            int rr = ty + i * 8;
            sm[rr][tx] = W[(size_t)(k0 + rr) * CC + n0 + tx];
        }
        __syncthreads();
#pragma unroll
        for (int i = 0; i < 4; i++) {
            int rr = ty + i * 8;
            g_wt[(size_t)slot * WSLOT + (size_t)(n0 + rr) * K + k0 + tx] = sm[tx][rr];
        }
        return;
    }
    {                                       // bias fuse
        int i = (bid - 5632) * 256 + t;
        float v = 0.0f;
        if (i < 512) v = bq[i];
        else if (i >= 1024) v = bv[i - 1024];
        g_bqkv[i] = v;
    }
}

// ---------------------------------------------------------------------------
// 1xTF32 GEMM body (unchanged, proven at plateau)
// ---------------------------------------------------------------------------
#define TPAD 36
#define ATILE (64 * TPAD * 4)
#define BTILE (128 * TPAD * 4)
#define TSMEM (2 * ATILE + 2 * BTILE)   // 55296 B

#define MMA1688T(d, a, b) \
    asm volatile( \
        "mma.sync.aligned.m16n8k8.row.col.f32.tf32.tf32.f32 " \
        "{%0,%1,%2,%3}, {%4,%5,%6,%7}, {%8,%9}, {%0,%1,%2,%3};" \
        : "+f"((d)[0]), "+f"((d)[1]), "+f"((d)[2]), "+f"((d)[3]) \
        : "r"((a)[0]), "r"((a)[1]), "r"((a)[2]), "r"((a)[3]), \
          "r"((b)[0]), "r"((b)[1]))

__device__ __forceinline__ void gemm_body(
    const float* __restrict__ A, const float* __restrict__ Bt,
    const float* __restrict__ bias, const float* __restrict__ resid,
    float* __restrict__ Cf, float* __restrict__ C2, float* __restrict__ C3,
    int K, int epi, int bx, int by, float* smf)
{
    uint32_t sbase = smem_u32(smf);
    int t = threadIdx.x, lane = t & 31, wid = t >> 5;
    int wm = wid >> 2;
    int wn = wid & 3;
    int m0 = by * 64, n0 = bx * 128;
    int gr = lane >> 2, gc = lane & 3;

    float acc[2][4][4];
#pragma unroll
    for (int mi = 0; mi < 2; mi++)
#pragma unroll
        for (int ni = 0; ni < 4; ni++)
#pragma unroll
            for (int j = 0; j < 4; j++) acc[mi][ni][j] = 0.0f;

    int nch = K >> 5;

    auto load_chunk = [&](int ch, int buf) {
        int k0 = ch << 5;
#pragma unroll
        for (int i = 0; i < 2; i++) {
            int idx = t + i * 256;
            int row = idx >> 3;
            int c   = idx & 7;
            uint32_t off = (uint32_t)(row * TPAD * 4 + c * 16);
            cp16(sbase + buf * ATILE + off,
                 A + (size_t)(m0 + row) * K + k0 + c * 4);
        }
#pragma unroll
        for (int i = 0; i < 4; i++) {
            int idx = t + i * 256;
            int row = idx >> 3;
            int c   = idx & 7;
            uint32_t off = (uint32_t)(row * TPAD * 4 + c * 16);
            cp16(sbase + 2 * ATILE + buf * BTILE + off,
                 Bt + (size_t)(n0 + row) * K + k0 + c * 4);
        }
        CP_COMMIT();
    };

    load_chunk(0, 0);
    load_chunk(1, 1);

    for (int ch = 0; ch < nch; ch++) {
        if (ch + 1 < nch) { CP_WAIT(1); } else { CP_WAIT(0); }
        __syncthreads();

        int buf = ch & 1;
        const float* sA = smf + (buf * ATILE >> 2);
        const float* sB = smf + ((2 * ATILE + buf * BTILE) >> 2);

#pragma unroll
        for (int ks = 0; ks < 4; ks++) {
            int kk = ks * 8;
            uint32_t af[2][4], bf[4][2];
#pragma unroll
            for (int mi = 0; mi < 2; mi++) {
                int base = (wm * 32 + mi * 16 + gr) * TPAD + kk;
                af[mi][0] = to_tf32(sA[base + gc]);
                af[mi][1] = to_tf32(sA[base + 8 * TPAD + gc]);
                af[mi][2] = to_tf32(sA[base + gc + 4]);
                af[mi][3] = to_tf32(sA[base + 8 * TPAD + gc + 4]);
            }
#pragma unroll
            for (int ni = 0; ni < 4; ni++) {
                int base = (wn * 32 + ni * 8 + gr) * TPAD + kk;
                bf[ni][0] = to_tf32(sB[base + gc]);
                bf[ni][1] = to_tf32(sB[base + gc + 4]);
            }
#pragma unroll
            for (int mi = 0; mi < 2; mi++)
#pragma unroll
                for (int ni = 0; ni < 4; ni++)
                    MMA1688T(acc[mi][ni], af[mi], bf[ni]);
        }
        __syncthreads();
        if (ch + 2 < nch) load_chunk(ch + 2, buf);
    }

#pragma unroll
    for (int mi = 0; mi < 2; mi++) {
#pragma unroll
        for (int ni = 0; ni < 4; ni++) {
            int row0 = m0 + wm * 32 + mi * 16 + gr;
            int col  = n0 + wn * 32 + ni * 8 + gc * 2;
#pragma unroll
            for (int half = 0; half < 2; half++) {
                int row = row0 + half * 8;
                float v0 = acc[mi][ni][half * 2 + 0];
                float v1 = acc[mi][ni][half * 2 + 1];
                if (bias) { v0 += bias[col]; v1 += bias[col + 1]; }
                if (epi == 1) {
                    v0 = v0 / (1.0f + expf(-v0));
                    v1 = v1 / (1.0f + expf(-v1));
                }
                if (epi == 3) {
                    int seg = col >> 9;
                    float* dst = (seg == 0) ? Cf : (seg == 1) ? C2 : C3;
                    size_t o = (size_t)row * CC + (col & 511);
                    *(float2*)(dst + o) = make_float2(v0, v1);
                } else {
                    size_t o = (size_t)row * CC + col;
                    if (epi == 2) {
                        v0 += resid[o];
                        v1 += resid[o + 1];
                    }
                    *(float2*)(Cf + o) = make_float2(v0, v1);
                }
            }
        }
    }
}

// Node 2 — QKV (768 blocks) + MLP1 (256 blocks) fused
__global__ __launch_bounds__(256, 2) void gemm_qkv_mlp1(
    const float* __restrict__ query, const float* __restrict__ b1)
{
    extern __shared__ float smf[];
    int bid = blockIdx.x;
    if (bid < 768) {
        gemm_body(query, g_wt + 2 * WSLOT, g_bqkv, nullptr,
                  g_q, g_k, g_v, CC, 3, bid % 12, bid / 12, smf);
    } else {
        int b2 = bid - 768;
        gemm_body(g_emb, g_wt + 0 * WSLOT, b1, nullptr,
                  g_hid, nullptr, nullptr, FREQE, 1, b2 & 3, b2 >> 2, smf);
    }
}

// Node 3 — MLP2
__global__ __launch_bounds__(256, 2) void gemm_mlp2(const float* __restrict__ b2)
{
    extern __shared__ float smf[];
    int bid = blockIdx.x;
    gemm_body(g_hid, g_wt + 1 * WSLOT, b2, nullptr,
              g_pe, nullptr, nullptr, CC, 0, bid & 3, bid >> 2, smf);
}

// Node 5 — output projection + bias + residual
__global__ __launch_bounds__(256, 2) void gemm_out(
    const float* __restrict__ bo, const float* __restrict__ query,
    float* __restrict__ out)
{
    extern __shared__ float smf[];
    int bid = blockIdx.x;
    gemm_body(g_x, g_wt + 5 * WSLOT, bo, query,
              out, nullptr, nullptr, CC, 2, bid & 3, bid >> 2, smf);
}

// ---------------------------------------------------------------------------
// Node 4 — phase-structured attention, conflict-free smem layouts.
// Block = (2 batches, head); grid (32, 8); 256 threads; 2 CTAs/SM.
// pe rows padded to 80 floats: phase-1 LDS.128 perfectly conflict-free.
// q rows 64 floats: broadcast reads (all m-threads same address).
// s rows 68 floats: phase-3 reads are warp-uniform broadcast.
// Phase 3: thread (n-half, b, d) holds V column in vreg[64] — no shfl.
// ---------------------------------------------------------------------------
#define PROW 80
#define PTL  (64 * PROW)                 // 5120 floats
#define QTL  (64 * 64)                   // 4096 floats
#define SROW 68
#define STL  (64 * SROW)                 // 4352 floats
#define ATTN_SMEM2 ((2 * PTL + 2 * QTL + 2 * STL) * 4)   // 108544 B

__global__ __launch_bounds__(256, 2) void attn_kernel() {
    extern __shared__ float smf[];
    float* pe_sm = smf;                      // [2][PTL]
    float* q_sm  = smf + 2 * PTL;            // [2][QTL]
    float* s_sm  = smf + 2 * PTL + 2 * QTL;  // [2][STL]

    uint32_t pe_u = smem_u32(pe_sm);
    uint32_t q_u  = smem_u32(q_sm);

    int h  = blockIdx.y;
    int b0 = blockIdx.x * 2;
    int t  = threadIdx.x;

    // ---- stage K (into pe bufs) + Q (into q_sm), both batches ----
#pragma unroll
    for (int i = 0; i < 8; i++) {
        int c = t + i * 256;             // 0..2047
        int b = c >> 10;
        int r = (c >> 4) & 63;
        int j = c & 15;
        size_t goff = ((size_t)((b0 + b) * 64 + r)) * 512 + h * 64 + j * 4;
        cp16(pe_u + (uint32_t)((b * PTL + r * PROW) * 4 + j * 16), g_k + goff);
        cp16(q_u  + (uint32_t)((b * QTL + r * 64)   * 4 + j * 16), g_q + goff);
    }
    CP_COMMIT();
    CP_WAIT(0);
    __syncthreads();

    // ---- K into registers: thread (m = t>>2, dq = t&3) ----
    int m  = t >> 2;
    int dq = t & 3;
    float4 kreg[2][4];
#pragma unroll
    for (int b = 0; b < 2; b++)
#pragma unroll
        for (int c = 0; c < 4; c++)
            kreg[b][c] = *(const float4*)&pe_sm[b * PTL + m * PROW + 4 * dq + 16 * c];
    __syncthreads();

    // ---- pe staging (double-buffered) ----
    auto stage_pe = [&](int n) {
        int buf = n & 1;
#pragma unroll
        for (int i = 0; i < 4; i++) {
            int c = t + i * 256;         // 0..1023
            int r = c >> 4;
            int j = c & 15;
            cp16(pe_u + (uint32_t)((buf * PTL + r * PROW) * 4 + j * 16),
                 g_pe + ((size_t)(n * 64 + r)) * 512 + h * 64 + j * 4);
        }
        CP_COMMIT();
    };
    stage_pe(0);
    stage_pe(1);

    // ---- Phase 1: scores ----
    for (int n = 0; n < 64; n++) {
        if (n < 62) { CP_WAIT(1); } else { CP_WAIT(0); }
        __syncthreads();

        int buf = n & 1;
        float p0 = 0.0f, p1 = 0.0f;
        const float* peb = &pe_sm[buf * PTL + m * PROW + 4 * dq];
        const float* qb0 = &q_sm[0 * QTL + n * 64 + 4 * dq];
        const float* qb1 = &q_sm[1 * QTL + n * 64 + 4 * dq];
#pragma unroll
        for (int c = 0; c < 4; c++) {
            float4 pe4 = *(const float4*)(peb + 16 * c);
            float4 q0  = *(const float4*)(qb0 + 16 * c);
            float4 q1  = *(const float4*)(qb1 + 16 * c);
            p0 = fmaf(q0.x * kreg[0][c].x, pe4.x, p0);
            p0 = fmaf(q0.y * kreg[0][c].y, pe4.y, p0);
            p0 = fmaf(q0.z * kreg[0][c].z, pe4.z, p0);
            p0 = fmaf(q0.w * kreg[0][c].w, pe4.w, p0);
            p1 = fmaf(q1.x * kreg[1][c].x, pe4.x, p1);
            p1 = fmaf(q1.y * kreg[1][c].y, pe4.y, p1);
            p1 = fmaf(q1.z * kreg[1][c].z, pe4.z, p1);
            p1 = fmaf(q1.w * kreg[1][c].w, pe4.w, p1);
        }
        p0 += __shfl_xor_sync(0xffffffffu, p0, 1);
        p0 += __shfl_xor_sync(0xffffffffu, p0, 2);
        p1 += __shfl_xor_sync(0xffffffffu, p1, 1);
        p1 += __shfl_xor_sync(0xffffffffu, p1, 2);
        if (dq == 0) {
            s_sm[0 * STL + n * SROW + m] = p0 * 0.125f;
            s_sm[1 * STL + n * SROW + m] = p1 * 0.125f;
        }
        __syncthreads();
        if (n + 2 < 64) stage_pe(n + 2);
    }

    // ---- stage V into freed pe buffers (overlaps with softmax) ----
#pragma unroll
    for (int i = 0; i < 8; i++) {
        int c = t + i * 256;
        int b = c >> 10;
        int r = (c >> 4) & 63;
        int j = c & 15;
        cp16(pe_u + (uint32_t)((b * PTL + r * PROW) * 4 + j * 16),
             g_v + ((size_t)((b0 + b) * 64 + r)) * 512 + h * 64 + j * 4);
    }
    CP_COMMIT();

    // ---- Phase 2: softmax, thread (b, n, half) owns 32 entries ----
    {
        int b  = t >> 7;
        int n  = (t >> 1) & 63;
        int hf = t & 1;
        float* row = &s_sm[b * STL + n * SROW + hf * 32];
        float4 e[8];
        float mx = -1e30f;
#pragma unroll
        for (int i = 0; i < 8; i++) {
            e[i] = *(const float4*)(row + i * 4);
            mx = fmaxf(mx, fmaxf(fmaxf(e[i].x, e[i].y), fmaxf(e[i].z, e[i].w)));
        }
        mx = fmaxf(mx, __shfl_xor_sync(0xffffffffu, mx, 1));
        float sum = 0.0f;
#pragma unroll
        for (int i = 0; i < 8; i++) {
            e[i].x = __expf(e[i].x - mx); e[i].y = __expf(e[i].y - mx);
            e[i].z = __expf(e[i].z - mx); e[i].w = __expf(e[i].w - mx);
            sum += e[i].x + e[i].y + e[i].z + e[i].w;
        }
        sum += __shfl_xor_sync(0xffffffffu, sum, 1);
        float inv = 1.0f / sum;
#pragma unroll
        for (int i = 0; i < 8; i++) {
            e[i].x *= inv; e[i].y *= inv; e[i].z *= inv; e[i].w *= inv;
            *(float4*)(row + i * 4) = e[i];
        }
    }

    CP_WAIT(0);
    __syncthreads();   // V staged + softmax stores visible

    // ---- Phase 3: AV. thread (nh = t>>7, vb = (t>>6)&1, d = t&63) ----
    {
        int nh = t >> 7;
        int vb = (t >> 6) & 1;
        int d  = t & 63;

        float vreg[64];
#pragma unroll
        for (int mm = 0; mm < 64; mm++)
            vreg[mm] = pe_sm[vb * PTL + mm * PROW + d];

        int n0 = nh * 32;
        for (int n = n0; n < n0 + 32; n++) {
            const float* sp = &s_sm[vb * STL + n * SROW];
            float acc = 0.0f;
#pragma unroll
            for (int c = 0; c < 16; c++) {
                float4 s4 = *(const float4*)(sp + c * 4);
                acc = fmaf(s4.x, vreg[c * 4 + 0], acc);
                acc = fmaf(s4.y, vreg[c * 4 + 1], acc);
                acc = fmaf(s4.z, vreg[c * 4 + 2], acc);
                acc = fmaf(s4.w, vreg[c * 4 + 3], acc);
            }
            g_x[((size_t)((b0 + vb) * 64 + n)) * 512 + h * 64 + d] = acc;
        }
    }
}

// ---------------------------------------------------------------------------
// Launch — 5 nodes, single stream.
// ---------------------------------------------------------------------------
extern "C" void kernel_launch(void* const* d_in, const int* in_sizes, int n_in,
                              void* d_out, int out_size)
{
    const float* query = (const float*)d_in[0];
    const float* qpos  = (const float*)d_in[1];
    const float* Wq    = (const float*)d_in[2];
    const float* bq    = (const float*)d_in[3];
    const float* Wk    = (const float*)d_in[4];
    const float* Wv    = (const float*)d_in[5];
    const float* bv    = (const float*)d_in[6];
    const float* Wo    = (const float*)d_in[7];
    const float* bo    = (const float*)d_in[8];
    const float* W1    = (const float*)d_in[9];
    const float* b1    = (const float*)d_in[10];
    const float* W2    = (const float*)d_in[11];
    const float* b2    = (const float*)d_in[12];
    float* out = (float*)d_out;

    static bool init = false;
    if (!init) {
        cudaFuncSetAttribute(gemm_qkv_mlp1, cudaFuncAttributeMaxDynamicSharedMemorySize, TSMEM);
        cudaFuncSetAttribute(gemm_mlp2,     cudaFuncAttributeMaxDynamicSharedMemorySize, TSMEM);
        cudaFuncSetAttribute(gemm_out,      cudaFuncAttributeMaxDynamicSharedMemorySize, TSMEM);
        cudaFuncSetAttribute(attn_kernel,   cudaFuncAttributeMaxDynamicSharedMemorySize, ATTN_SMEM2);
        init = true;
    }

    prep_kernel<<<PREP_BLOCKS, 256>>>(qpos, W1, W2, Wq, Wk, Wv, Wo, bq, bv);
    gemm_qkv_mlp1<<<1024, 256, TSMEM>>>(query, b1);
    gemm_mlp2<<<256, 256, TSMEM>>>(b2);
    attn_kernel<<<dim3(32, HH), 256, ATTN_SMEM2>>>();
    gemm_out<<<256, 256, TSMEM>>>(bo, query, out);
}

// round 13
// speedup vs baseline: 1.8888x; 1.0002x over previous
#include <cuda_runtime.h>
#include <math.h>
#include <stdint.h>

// Problem constants
#define BB    64
#define CC    512
#define HH    8
#define HD    64
#define FREQE 256
#define ROWS  4096   // B*N == N*M
#define WSLOT (CC * CC)

// ---------------------------------------------------------------------------
// Scratch (device globals; no allocation allowed)
// ---------------------------------------------------------------------------
__device__ float g_pe [ROWS * CC];
__device__ float g_q  [ROWS * CC];
__device__ float g_k  [ROWS * CC];
__device__ float g_v  [ROWS * CC];
__device__ float g_x  [ROWS * CC];
__device__ float g_emb[ROWS * FREQE];
__device__ float g_hid[ROWS * CC];
__device__ float g_bqkv[3 * CC];
__device__ float g_wt [6 * CC * CC];    // transposed W1,W2,Wq,Wk,Wv,Wo (fp32)

__device__ __forceinline__ uint32_t to_tf32(float x) {
    uint32_t u;
    asm("cvt.rna.tf32.f32 %0, %1;" : "=r"(u) : "f"(x));
    return u;
}

__device__ __forceinline__ uint32_t smem_u32(const void* p) {
    uint32_t a;
    asm("{ .reg .u64 t; cvta.to.shared.u64 t, %1; cvt.u32.u64 %0, t; }"
        : "=r"(a) : "l"(p));
    return a;
}

__device__ __forceinline__ void cp16(uint32_t dst, const void* src) {
    asm volatile("cp.async.cg.shared.global [%0], [%1], 16;" :: "r"(dst), "l"(src));
}
#define CP_COMMIT() asm volatile("cp.async.commit_group;" ::: "memory")
#define CP_WAIT(n)  asm volatile("cp.async.wait_group %0;" :: "n"(n) : "memory")

// ---------------------------------------------------------------------------
// Node 1 — prep: embedding + 6 weight transposes + fused qkv bias.
// ---------------------------------------------------------------------------
#define PREP_BLOCKS (4096 + 1536 + 6)

__global__ __launch_bounds__(256) void prep_kernel(
    const float* __restrict__ qpos,
    const float* __restrict__ W1, const float* __restrict__ W2,
    const float* __restrict__ Wq, const float* __restrict__ Wk,
    const float* __restrict__ Wv, const float* __restrict__ Wo,
    const float* __restrict__ bq, const float* __restrict__ bv)
{
    int bid = blockIdx.x;
    int t = threadIdx.x;

    if (bid < 4096) {                       // embedding (fast-math)
        int idx = bid * 256 + t;
        int p = idx >> 8;
        int j = idx & 255;
        float tp = qpos[p];
        int jj = j & 127;
        float f = __expf(-9.210340371976184f * (float)jj * (1.0f / 128.0f));
        float a = tp * f;
        float s, c;
        __sincosf(a, &s, &c);
        g_emb[idx] = (j < 128) ? c : s;
        return;
    }
    if (bid < 5632) {                       // weight transposes
        int bid2 = bid - 4096;
        int slot = bid2 >> 8;               // 0..5
        int r    = bid2 & 255;
        int k0 = (r & 15) * 32;
        int n0 = (r >> 4) * 32;
        int K = (slot == 0) ? FREQE : CC;
        if (k0 >= K) return;

        const float* W = (slot == 0) ? W1 : (slot == 1) ? W2 : (slot == 2) ? Wq
                       : (slot == 3) ? Wk : (slot == 4) ? Wv : Wo;

        __shared__ float sm[32][33];
        int tx = t & 31, ty = t >> 5;
#pragma unroll
        for (int i = 0; i < 4; i++) {
            int rr = ty + i * 8;
            sm[rr][tx] = W[(size_t)(k0 + rr) * CC + n0 + tx];
        }
        __syncthreads();
#pragma unroll
        for (int i = 0; i < 4; i++) {
            int rr = ty + i * 8;
            g_wt[(size_t)slot * WSLOT + (size_t)(n0 + rr) * K + k0 + tx] = sm[tx][rr];
        }
        return;
    }
    {                                       // bias fuse
        int i = (bid - 5632) * 256 + t;
        float v = 0.0f;
        if (i < 512) v = bq[i];
        else if (i >= 1024) v = bv[i - 1024];
        g_bqkv[i] = v;
    }
}

// ---------------------------------------------------------------------------
// 1xTF32 GEMM body (unchanged, proven at plateau)
// ---------------------------------------------------------------------------
#define TPAD 36
#define ATILE (64 * TPAD * 4)
#define BTILE (128 * TPAD * 4)
#define TSMEM (2 * ATILE + 2 * BTILE)   // 55296 B

#define MMA1688T(d, a, b) \
    asm volatile( \
        "mma.sync.aligned.m16n8k8.row.col.f32.tf32.tf32.f32 " \
        "{%0,%1,%2,%3}, {%4,%5,%6,%7}, {%8,%9}, {%0,%1,%2,%3};" \
        : "+f"((d)[0]), "+f"((d)[1]), "+f"((d)[2]), "+f"((d)[3]) \
        : "r"((a)[0]), "r"((a)[1]), "r"((a)[2]), "r"((a)[3]), \
          "r"((b)[0]), "r"((b)[1]))

__device__ __forceinline__ void gemm_body(
    const float* __restrict__ A, const float* __restrict__ Bt,
    const float* __restrict__ bias, const float* __restrict__ resid,
    float* __restrict__ Cf, float* __restrict__ C2, float* __restrict__ C3,
    int K, int epi, int bx, int by, float* smf)
{
    uint32_t sbase = smem_u32(smf);
    int t = threadIdx.x, lane = t & 31, wid = t >> 5;
    int wm = wid >> 2;
    int wn = wid & 3;
    int m0 = by * 64, n0 = bx * 128;
    int gr = lane >> 2, gc = lane & 3;

    float acc[2][4][4];
#pragma unroll
    for (int mi = 0; mi < 2; mi++)
#pragma unroll
        for (int ni = 0; ni < 4; ni++)
#pragma unroll
            for (int j = 0; j < 4; j++) acc[mi][ni][j] = 0.0f;

    int nch = K >> 5;

    auto load_chunk = [&](int ch, int buf) {
        int k0 = ch << 5;
#pragma unroll
        for (int i = 0; i < 2; i++) {
            int idx = t + i * 256;
            int row = idx >> 3;
            int c   = idx & 7;
            uint32_t off = (uint32_t)(row * TPAD * 4 + c * 16);
            cp16(sbase + buf * ATILE + off,
                 A + (size_t)(m0 + row) * K + k0 + c * 4);
        }
#pragma unroll
        for (int i = 0; i < 4; i++) {
            int idx = t + i * 256;
            int row = idx >> 3;
            int c   = idx & 7;
            uint32_t off = (uint32_t)(row * TPAD * 4 + c * 16);
            cp16(sbase + 2 * ATILE + buf * BTILE + off,
                 Bt + (size_t)(n0 + row) * K + k0 + c * 4);
        }
        CP_COMMIT();
    };

    load_chunk(0, 0);
    load_chunk(1, 1);

    for (int ch = 0; ch < nch; ch++) {
        if (ch + 1 < nch) { CP_WAIT(1); } else { CP_WAIT(0); }
        __syncthreads();

        int buf = ch & 1;
        const float* sA = smf + (buf * ATILE >> 2);
        const float* sB = smf + ((2 * ATILE + buf * BTILE) >> 2);

#pragma unroll
        for (int ks = 0; ks < 4; ks++) {
            int kk = ks * 8;
            uint32_t af[2][4], bf[4][2];
#pragma unroll
            for (int mi = 0; mi < 2; mi++) {
                int base = (wm * 32 + mi * 16 + gr) * TPAD + kk;
                af[mi][0] = to_tf32(sA[base + gc]);
                af[mi][1] = to_tf32(sA[base + 8 * TPAD + gc]);
                af[mi][2] = to_tf32(sA[base + gc + 4]);
                af[mi][3] = to_tf32(sA[base + 8 * TPAD + gc + 4]);
            }
#pragma unroll
            for (int ni = 0; ni < 4; ni++) {
                int base = (wn * 32 + ni * 8 + gr) * TPAD + kk;
                bf[ni][0] = to_tf32(sB[base + gc]);
                bf[ni][1] = to_tf32(sB[base + gc + 4]);
            }
#pragma unroll
            for (int mi = 0; mi < 2; mi++)
#pragma unroll
                for (int ni = 0; ni < 4; ni++)
                    MMA1688T(acc[mi][ni], af[mi], bf[ni]);
        }
        __syncthreads();
        if (ch + 2 < nch) load_chunk(ch + 2, buf);
    }

#pragma unroll
    for (int mi = 0; mi < 2; mi++) {
#pragma unroll
        for (int ni = 0; ni < 4; ni++) {
            int row0 = m0 + wm * 32 + mi * 16 + gr;
            int col  = n0 + wn * 32 + ni * 8 + gc * 2;
#pragma unroll
            for (int half = 0; half < 2; half++) {
                int row = row0 + half * 8;
                float v0 = acc[mi][ni][half * 2 + 0];
                float v1 = acc[mi][ni][half * 2 + 1];
                if (bias) { v0 += bias[col]; v1 += bias[col + 1]; }
                if (epi == 1) {
                    v0 = v0 / (1.0f + expf(-v0));
                    v1 = v1 / (1.0f + expf(-v1));
                }
                if (epi == 3) {
                    int seg = col >> 9;
                    float* dst = (seg == 0) ? Cf : (seg == 1) ? C2 : C3;
                    size_t o = (size_t)row * CC + (col & 511);
                    *(float2*)(dst + o) = make_float2(v0, v1);
                } else {
                    size_t o = (size_t)row * CC + col;
                    if (epi == 2) {
                        v0 += resid[o];
                        v1 += resid[o + 1];
                    }
                    *(float2*)(Cf + o) = make_float2(v0, v1);
                }
            }
        }
    }
}

// Node 2 — QKV (768 blocks) + MLP1 (256 blocks) fused
__global__ __launch_bounds__(256, 2) void gemm_qkv_mlp1(
    const float* __restrict__ query, const float* __restrict__ b1)
{
    extern __shared__ float smf[];
    int bid = blockIdx.x;
    if (bid < 768) {
        gemm_body(query, g_wt + 2 * WSLOT, g_bqkv, nullptr,
                  g_q, g_k, g_v, CC, 3, bid % 12, bid / 12, smf);
    } else {
        int b2 = bid - 768;
        gemm_body(g_emb, g_wt + 0 * WSLOT, b1, nullptr,
                  g_hid, nullptr, nullptr, FREQE, 1, b2 & 3, b2 >> 2, smf);
    }
}

// Node 3 — MLP2
__global__ __launch_bounds__(256, 2) void gemm_mlp2(const float* __restrict__ b2)
{
    extern __shared__ float smf[];
    int bid = blockIdx.x;
    gemm_body(g_hid, g_wt + 1 * WSLOT, b2, nullptr,
              g_pe, nullptr, nullptr, CC, 0, bid & 3, bid >> 2, smf);
}

// Node 5 — output projection + bias + residual
__global__ __launch_bounds__(256, 2) void gemm_out(
    const float* __restrict__ bo, const float* __restrict__ query,
    float* __restrict__ out)
{
    extern __shared__ float smf[];
    int bid = blockIdx.x;
    gemm_body(g_x, g_wt + 5 * WSLOT, bo, query,
              out, nullptr, nullptr, CC, 2, bid & 3, bid >> 2, smf);
}

// ---------------------------------------------------------------------------
// Node 4 — phase-structured attention, 4 batches/block, 512 threads, 1 CTA/SM.
// Grid (16, 8). smem: pe[2][PTL] (PROW=80, conflict-free) | q[4][QTL] | s[4][STL].
// Phase 1: thread (bp, m, dq) computes scores for batches bp*2, bp*2+1.
// Phase 2: thread (b, n, half) softmax. Phase 3: thread (nh, vb, d), V in q buf.
// ---------------------------------------------------------------------------
#define PROW 80
#define PTL  (64 * PROW)                 // 5120 floats
#define QTL  (64 * 64)                   // 4096 floats
#define SROW 68
#define STL  (64 * SROW)                 // 4352 floats
#define ATTN_SMEM2 ((2 * PTL + 4 * QTL + 4 * STL) * 4)   // 176128 B

__global__ __launch_bounds__(512, 1) void attn_kernel() {
    extern __shared__ float smf[];
    float* pe_sm = smf;                      // [2][PTL]
    float* q_sm  = smf + 2 * PTL;            // [4][QTL]  (K/Q staging, later V)
    float* s_sm  = smf + 2 * PTL + 4 * QTL;  // [4][STL]

    uint32_t pe_u = smem_u32(pe_sm);
    uint32_t q_u  = smem_u32(q_sm);

    int h  = blockIdx.y;
    int b0 = blockIdx.x * 4;
    int t  = threadIdx.x;

    // phase-1 mapping
    int bp = t >> 8;          // 0..1 -> batches bp*2, bp*2+1
    int m  = (t >> 2) & 63;
    int dq = t & 3;

    float4 kreg[2][4];

    // ---- K staging round A: batches 0,1 -> pe bufs ----
#pragma unroll
    for (int i = 0; i < 4; i++) {
        int c = t + i * 512;             // 0..2047
        int b = c >> 10;                 // 0..1
        int r = (c >> 4) & 63;
        int j = c & 15;
        cp16(pe_u + (uint32_t)((b * PTL + r * PROW) * 4 + j * 16),
             g_k + ((size_t)((b0 + b) * 64 + r)) * 512 + h * 64 + j * 4);
    }
    CP_COMMIT(); CP_WAIT(0);
    __syncthreads();
    if (bp == 0) {
#pragma unroll
        for (int bb = 0; bb < 2; bb++)
#pragma unroll
            for (int c = 0; c < 4; c++)
                kreg[bb][c] = *(const float4*)&pe_sm[bb * PTL + m * PROW + 4 * dq + 16 * c];
    }
    __syncthreads();

    // ---- K staging round B (batches 2,3) + Q staging (all 4 batches) ----
#pragma unroll
    for (int i = 0; i < 4; i++) {
        int c = t + i * 512;
        int b = c >> 10;                 // 0..1 -> batches 2,3
        int r = (c >> 4) & 63;
        int j = c & 15;
        cp16(pe_u + (uint32_t)((b * PTL + r * PROW) * 4 + j * 16),
             g_k + ((size_t)((b0 + 2 + b) * 64 + r)) * 512 + h * 64 + j * 4);
    }
#pragma unroll
    for (int i = 0; i < 8; i++) {
        int c = t + i * 512;             // 0..4095
        int b = c >> 10;                 // 0..3
        int r = (c >> 4) & 63;
        int j = c & 15;
        cp16(q_u + (uint32_t)((b * QTL + r * 64) * 4 + j * 16),
             g_q + ((size_t)((b0 + b) * 64 + r)) * 512 + h * 64 + j * 4);
    }
    CP_COMMIT(); CP_WAIT(0);
    __syncthreads();
    if (bp == 1) {
#pragma unroll
        for (int bb = 0; bb < 2; bb++)
#pragma unroll
            for (int c = 0; c < 4; c++)
                kreg[bb][c] = *(const float4*)&pe_sm[bb * PTL + m * PROW + 4 * dq + 16 * c];
    }
    __syncthreads();

    // ---- pe staging (double-buffered), 1024 chunks / 512 threads ----
    auto stage_pe = [&](int n) {
        int buf = n & 1;
#pragma unroll
        for (int i = 0; i < 2; i++) {
            int c = t + i * 512;         // 0..1023
            int r = c >> 4;
            int j = c & 15;
            cp16(pe_u + (uint32_t)((buf * PTL + r * PROW) * 4 + j * 16),
                 g_pe + ((size_t)(n * 64 + r)) * 512 + h * 64 + j * 4);
        }
        CP_COMMIT();
    };
    stage_pe(0);
    stage_pe(1);

    // ---- Phase 1: scores ----
    for (int n = 0; n < 64; n++) {
        if (n < 62) { CP_WAIT(1); } else { CP_WAIT(0); }
        __syncthreads();

        int buf = n & 1;
        float p0 = 0.0f, p1 = 0.0f;
        const float* peb = &pe_sm[buf * PTL + m * PROW + 4 * dq];
        const float* qb0 = &q_sm[(bp * 2 + 0) * QTL + n * 64 + 4 * dq];
        const float* qb1 = &q_sm[(bp * 2 + 1) * QTL + n * 64 + 4 * dq];
#pragma unroll
        for (int c = 0; c < 4; c++) {
            float4 pe4 = *(const float4*)(peb + 16 * c);
            float4 q0  = *(const float4*)(qb0 + 16 * c);
            float4 q1  = *(const float4*)(qb1 + 16 * c);
            p0 = fmaf(q0.x * kreg[0][c].x, pe4.x, p0);
            p0 = fmaf(q0.y * kreg[0][c].y, pe4.y, p0);
            p0 = fmaf(q0.z * kreg[0][c].z, pe4.z, p0);
            p0 = fmaf(q0.w * kreg[0][c].w, pe4.w, p0);
            p1 = fmaf(q1.x * kreg[1][c].x, pe4.x, p1);
            p1 = fmaf(q1.y * kreg[1][c].y, pe4.y, p1);
            p1 = fmaf(q1.z * kreg[1][c].z, pe4.z, p1);
            p1 = fmaf(q1.w * kreg[1][c].w, pe4.w, p1);
        }
        p0 += __shfl_xor_sync(0xffffffffu, p0, 1);
        p0 += __shfl_xor_sync(0xffffffffu, p0, 2);
        p1 += __shfl_xor_sync(0xffffffffu, p1, 1);
        p1 += __shfl_xor_sync(0xffffffffu, p1, 2);
        if (dq == 0) {
            s_sm[(bp * 2 + 0) * STL + n * SROW + m] = p0 * 0.125f;
            s_sm[(bp * 2 + 1) * STL + n * SROW + m] = p1 * 0.125f;
        }
        __syncthreads();
        if (n + 2 < 64) stage_pe(n + 2);
    }

    // ---- stage V (4 batches) into q_sm (free after phase 1) ----
#pragma unroll
    for (int i = 0; i < 8; i++) {
        int c = t + i * 512;             // 0..4095
        int b = c >> 10;
        int r = (c >> 4) & 63;
        int j = c & 15;
        cp16(q_u + (uint32_t)((b * QTL + r * 64) * 4 + j * 16),
             g_v + ((size_t)((b0 + b) * 64 + r)) * 512 + h * 64 + j * 4);
    }
    CP_COMMIT();

    // ---- Phase 2: softmax, thread (b, n, half) ----
    {
        int b  = t >> 7;
        int n  = (t >> 1) & 63;
        int hf = t & 1;
        float* row = &s_sm[b * STL + n * SROW + hf * 32];
        float4 e[8];
        float mx = -1e30f;
#pragma unroll
        for (int i = 0; i < 8; i++) {
            e[i] = *(const float4*)(row + i * 4);
            mx = fmaxf(mx, fmaxf(fmaxf(e[i].x, e[i].y), fmaxf(e[i].z, e[i].w)));
        }
        mx = fmaxf(mx, __shfl_xor_sync(0xffffffffu, mx, 1));
        float sum = 0.0f;
#pragma unroll
        for (int i = 0; i < 8; i++) {
            e[i].x = __expf(e[i].x - mx); e[i].y = __expf(e[i].y - mx);
            e[i].z = __expf(e[i].z - mx); e[i].w = __expf(e[i].w - mx);
            sum += e[i].x + e[i].y + e[i].z + e[i].w;
        }
        sum += __shfl_xor_sync(0xffffffffu, sum, 1);
        float inv = 1.0f / sum;
#pragma unroll
        for (int i = 0; i < 8; i++) {
            e[i].x *= inv; e[i].y *= inv; e[i].z *= inv; e[i].w *= inv;
            *(float4*)(row + i * 4) = e[i];
        }
    }

    CP_WAIT(0);
    __syncthreads();   // V staged + softmax stores visible

    // ---- Phase 3: AV. thread (nh = t>>8, vb = (t>>6)&3, d = t&63) ----
    {
        int nh = t >> 8;
        int vb = (t >> 6) & 3;
        int d  = t & 63;

        float vreg[64];
#pragma unroll
        for (int mm = 0; mm < 64; mm++)
            vreg[mm] = q_sm[vb * QTL + mm * 64 + d];

        int n0 = nh * 32;
        for (int n = n0; n < n0 + 32; n++) {
            const float* sp = &s_sm[vb * STL + n * SROW];
            float acc = 0.0f;
#pragma unroll
            for (int c = 0; c < 16; c++) {
                float4 s4 = *(const float4*)(sp + c * 4);
                acc = fmaf(s4.x, vreg[c * 4 + 0], acc);
                acc = fmaf(s4.y, vreg[c * 4 + 1], acc);
                acc = fmaf(s4.z, vreg[c * 4 + 2], acc);
                acc = fmaf(s4.w, vreg[c * 4 + 3], acc);
            }
            g_x[((size_t)((b0 + vb) * 64 + n)) * 512 + h * 64 + d] = acc;
        }
    }
}

// ---------------------------------------------------------------------------
// Launch — 5 nodes, single stream.
// ---------------------------------------------------------------------------
extern "C" void kernel_launch(void* const* d_in, const int* in_sizes, int n_in,
                              void* d_out, int out_size)
{
    const float* query = (const float*)d_in[0];
    const float* qpos  = (const float*)d_in[1];
    const float* Wq    = (const float*)d_in[2];
    const float* bq    = (const float*)d_in[3];
    const float* Wk    = (const float*)d_in[4];
    const float* Wv    = (const float*)d_in[5];
    const float* bv    = (const float*)d_in[6];
    const float* Wo    = (const float*)d_in[7];
    const float* bo    = (const float*)d_in[8];
    const float* W1    = (const float*)d_in[9];
    const float* b1    = (const float*)d_in[10];
    const float* W2    = (const float*)d_in[11];
    const float* b2    = (const float*)d_in[12];
    float* out = (float*)d_out;

    static bool init = false;
    if (!init) {
        cudaFuncSetAttribute(gemm_qkv_mlp1, cudaFuncAttributeMaxDynamicSharedMemorySize, TSMEM);
        cudaFuncSetAttribute(gemm_mlp2,     cudaFuncAttributeMaxDynamicSharedMemorySize, TSMEM);
        cudaFuncSetAttribute(gemm_out,      cudaFuncAttributeMaxDynamicSharedMemorySize, TSMEM);
        cudaFuncSetAttribute(attn_kernel,   cudaFuncAttributeMaxDynamicSharedMemorySize, ATTN_SMEM2);
        init = true;
    }

    prep_kernel<<<PREP_BLOCKS, 256>>>(qpos, W1, W2, Wq, Wk, Wv, Wo, bq, bv);
    gemm_qkv_mlp1<<<1024, 256, TSMEM>>>(query, b1);
    gemm_mlp2<<<256, 256, TSMEM>>>(b2);
    attn_kernel<<<dim3(16, HH), 512, ATTN_SMEM2>>>();
    gemm_out<<<256, 256, TSMEM>>>(bo, query, out);
}

// round 14
// speedup vs baseline: 2.0126x; 1.0656x over previous
#include <cuda_runtime.h>
#include <math.h>
#include <stdint.h>

// Problem constants
#define BB    64
#define CC    512
#define HH    8
#define HD    64
#define FREQE 256
#define ROWS  4096   // B*N == N*M
#define WSLOT (CC * CC)

// ---------------------------------------------------------------------------
// Scratch (device globals; no allocation allowed)
// ---------------------------------------------------------------------------
__device__ float g_pe [ROWS * CC];
__device__ float g_q  [ROWS * CC];
__device__ float g_k  [ROWS * CC];
__device__ float g_v  [ROWS * CC];
__device__ float g_x  [ROWS * CC];
__device__ float g_emb[ROWS * FREQE];
__device__ float g_hid[ROWS * CC];
__device__ float g_bqkv[3 * CC];
__device__ float g_wt [6 * CC * CC];    // transposed W1,W2,Wq,Wk,Wv,Wo (fp32)

__device__ __forceinline__ uint32_t to_tf32(float x) {
    uint32_t u;
    asm("cvt.rna.tf32.f32 %0, %1;" : "=r"(u) : "f"(x));
    return u;
}

__device__ __forceinline__ uint32_t smem_u32(const void* p) {
    uint32_t a;
    asm("{ .reg .u64 t; cvta.to.shared.u64 t, %1; cvt.u32.u64 %0, t; }"
        : "=r"(a) : "l"(p));
    return a;
}

__device__ __forceinline__ void cp16(uint32_t dst, const void* src) {
    asm volatile("cp.async.cg.shared.global [%0], [%1], 16;" :: "r"(dst), "l"(src));
}
#define CP_COMMIT() asm volatile("cp.async.commit_group;" ::: "memory")
#define CP_WAIT(n)  asm volatile("cp.async.wait_group %0;" :: "n"(n) : "memory")

// ---------------------------------------------------------------------------
// prep: embedding + 6 weight transposes + fused qkv bias.
// ---------------------------------------------------------------------------
#define PREP_BLOCKS (4096 + 1536 + 6)

__global__ __launch_bounds__(256) void prep_kernel(
    const float* __restrict__ qpos,
    const float* __restrict__ W1, const float* __restrict__ W2,
    const float* __restrict__ Wq, const float* __restrict__ Wk,
    const float* __restrict__ Wv, const float* __restrict__ Wo,
    const float* __restrict__ bq, const float* __restrict__ bv)
{
    int bid = blockIdx.x;
    int t = threadIdx.x;

    if (bid < 4096) {                       // embedding (fast-math)
        int idx = bid * 256 + t;
        int p = idx >> 8;
        int j = idx & 255;
        float tp = qpos[p];
        int jj = j & 127;
        float f = __expf(-9.210340371976184f * (float)jj * (1.0f / 128.0f));
        float a = tp * f;
        float s, c;
        __sincosf(a, &s, &c);
        g_emb[idx] = (j < 128) ? c : s;
        return;
    }
    if (bid < 5632) {                       // weight transposes
        int bid2 = bid - 4096;
        int slot = bid2 >> 8;               // 0..5
        int r    = bid2 & 255;
        int k0 = (r & 15) * 32;
        int n0 = (r >> 4) * 32;
        int K = (slot == 0) ? FREQE : CC;
        if (k0 >= K) return;

        const float* W = (slot == 0) ? W1 : (slot == 1) ? W2 : (slot == 2) ? Wq
                       : (slot == 3) ? Wk : (slot == 4) ? Wv : Wo;

        __shared__ float sm[32][33];
        int tx = t & 31, ty = t >> 5;
#pragma unroll
        for (int i = 0; i < 4; i++) {
            int rr = ty + i * 8;
            sm[rr][tx] = W[(size_t)(k0 + rr) * CC + n0 + tx];
        }
        __syncthreads();
#pragma unroll
        for (int i = 0; i < 4; i++) {
            int rr = ty + i * 8;
            g_wt[(size_t)slot * WSLOT + (size_t)(n0 + rr) * K + k0 + tx] = sm[tx][rr];
        }
        return;
    }
    {                                       // bias fuse
        int i = (bid - 5632) * 256 + t;
        float v = 0.0f;
        if (i < 512) v = bq[i];
        else if (i >= 1024) v = bv[i - 1024];
        g_bqkv[i] = v;
    }
}

// ---------------------------------------------------------------------------
// 1xTF32 GEMM body (proven at plateau)
// ---------------------------------------------------------------------------
#define TPAD 36
#define ATILE (64 * TPAD * 4)
#define BTILE (128 * TPAD * 4)
#define TSMEM (2 * ATILE + 2 * BTILE)   // 55296 B

#define MMA1688T(d, a, b) \
    asm volatile( \
        "mma.sync.aligned.m16n8k8.row.col.f32.tf32.tf32.f32 " \
        "{%0,%1,%2,%3}, {%4,%5,%6,%7}, {%8,%9}, {%0,%1,%2,%3};" \
        : "+f"((d)[0]), "+f"((d)[1]), "+f"((d)[2]), "+f"((d)[3]) \
        : "r"((a)[0]), "r"((a)[1]), "r"((a)[2]), "r"((a)[3]), \
          "r"((b)[0]), "r"((b)[1]))

__device__ __forceinline__ void gemm_body(
    const float* __restrict__ A, const float* __restrict__ Bt,
    const float* __restrict__ bias, const float* __restrict__ resid,
    float* __restrict__ Cf, float* __restrict__ C2, float* __restrict__ C3,
    int K, int epi, int bx, int by, float* smf)
{
    uint32_t sbase = smem_u32(smf);
    int t = threadIdx.x, lane = t & 31, wid = t >> 5;
    int wm = wid >> 2;
    int wn = wid & 3;
    int m0 = by * 64, n0 = bx * 128;
    int gr = lane >> 2, gc = lane & 3;

    float acc[2][4][4];
#pragma unroll
    for (int mi = 0; mi < 2; mi++)
#pragma unroll
        for (int ni = 0; ni < 4; ni++)
#pragma unroll
            for (int j = 0; j < 4; j++) acc[mi][ni][j] = 0.0f;

    int nch = K >> 5;

    auto load_chunk = [&](int ch, int buf) {
        int k0 = ch << 5;
#pragma unroll
        for (int i = 0; i < 2; i++) {
            int idx = t + i * 256;
            int row = idx >> 3;
            int c   = idx & 7;
            uint32_t off = (uint32_t)(row * TPAD * 4 + c * 16);
            cp16(sbase + buf * ATILE + off,
                 A + (size_t)(m0 + row) * K + k0 + c * 4);
        }
#pragma unroll
        for (int i = 0; i < 4; i++) {
            int idx = t + i * 256;
            int row = idx >> 3;
            int c   = idx & 7;
            uint32_t off = (uint32_t)(row * TPAD * 4 + c * 16);
            cp16(sbase + 2 * ATILE + buf * BTILE + off,
                 Bt + (size_t)(n0 + row) * K + k0 + c * 4);
        }
        CP_COMMIT();
    };

    load_chunk(0, 0);
    load_chunk(1, 1);

    for (int ch = 0; ch < nch; ch++) {
        if (ch + 1 < nch) { CP_WAIT(1); } else { CP_WAIT(0); }
        __syncthreads();

        int buf = ch & 1;
        const float* sA = smf + (buf * ATILE >> 2);
        const float* sB = smf + ((2 * ATILE + buf * BTILE) >> 2);

#pragma unroll
        for (int ks = 0; ks < 4; ks++) {
            int kk = ks * 8;
            uint32_t af[2][4], bf[4][2];
#pragma unroll
            for (int mi = 0; mi < 2; mi++) {
                int base = (wm * 32 + mi * 16 + gr) * TPAD + kk;
                af[mi][0] = to_tf32(sA[base + gc]);
                af[mi][1] = to_tf32(sA[base + 8 * TPAD + gc]);
                af[mi][2] = to_tf32(sA[base + gc + 4]);
                af[mi][3] = to_tf32(sA[base + 8 * TPAD + gc + 4]);
            }
#pragma unroll
            for (int ni = 0; ni < 4; ni++) {
                int base = (wn * 32 + ni * 8 + gr) * TPAD + kk;
                bf[ni][0] = to_tf32(sB[base + gc]);
                bf[ni][1] = to_tf32(sB[base + gc + 4]);
            }
#pragma unroll
            for (int mi = 0; mi < 2; mi++)
#pragma unroll
                for (int ni = 0; ni < 4; ni++)
                    MMA1688T(acc[mi][ni], af[mi], bf[ni]);
        }
        __syncthreads();
        if (ch + 2 < nch) load_chunk(ch + 2, buf);
    }

#pragma unroll
    for (int mi = 0; mi < 2; mi++) {
#pragma unroll
        for (int ni = 0; ni < 4; ni++) {
            int row0 = m0 + wm * 32 + mi * 16 + gr;
            int col  = n0 + wn * 32 + ni * 8 + gc * 2;
#pragma unroll
            for (int half = 0; half < 2; half++) {
                int row = row0 + half * 8;
                float v0 = acc[mi][ni][half * 2 + 0];
                float v1 = acc[mi][ni][half * 2 + 1];
                if (bias) { v0 += bias[col]; v1 += bias[col + 1]; }
                if (epi == 1) {
                    v0 = v0 / (1.0f + expf(-v0));
                    v1 = v1 / (1.0f + expf(-v1));
                }
                if (epi == 3) {
                    int seg = col >> 9;
                    float* dst = (seg == 0) ? Cf : (seg == 1) ? C2 : C3;
                    size_t o = (size_t)row * CC + (col & 511);
                    *(float2*)(dst + o) = make_float2(v0, v1);
                } else {
                    size_t o = (size_t)row * CC + col;
                    if (epi == 2) {
                        v0 += resid[o];
                        v1 += resid[o + 1];
                    }
                    *(float2*)(Cf + o) = make_float2(v0, v1);
                }
            }
        }
    }
}

// QKV GEMM (768 blocks)
__global__ __launch_bounds__(256, 2) void gemm_qkv(const float* __restrict__ query)
{
    extern __shared__ float smf[];
    int bid = blockIdx.x;
    gemm_body(query, g_wt + 2 * WSLOT, g_bqkv, nullptr,
              g_q, g_k, g_v, CC, 3, bid % 12, bid / 12, smf);
}

// MLP1 (256 blocks)
__global__ __launch_bounds__(256, 2) void gemm_mlp1(const float* __restrict__ b1)
{
    extern __shared__ float smf[];
    int bid = blockIdx.x;
    gemm_body(g_emb, g_wt + 0 * WSLOT, b1, nullptr,
              g_hid, nullptr, nullptr, FREQE, 1, bid & 3, bid >> 2, smf);
}

// MLP2 (256 blocks)
__global__ __launch_bounds__(256, 2) void gemm_mlp2(const float* __restrict__ b2)
{
    extern __shared__ float smf[];
    int bid = blockIdx.x;
    gemm_body(g_hid, g_wt + 1 * WSLOT, b2, nullptr,
              g_pe, nullptr, nullptr, CC, 0, bid & 3, bid >> 2, smf);
}

// output projection + bias + residual
__global__ __launch_bounds__(256, 2) void gemm_out(
    const float* __restrict__ bo, const float* __restrict__ query,
    float* __restrict__ out)
{
    extern __shared__ float smf[];
    int bid = blockIdx.x;
    gemm_body(g_x, g_wt + 5 * WSLOT, bo, query,
              out, nullptr, nullptr, CC, 2, bid & 3, bid >> 2, smf);
}

// ---------------------------------------------------------------------------
// Attention: 4 batches/block, 512 threads, 1 CTA/SM, grid (16, 8).
// pe ring buffer x4 (PROW=80, conflict-free) -> ONE barrier per n-iteration.
// smem: pe[4][PTL] | q[4][QTL] | s[4][STL] = 212 KB.
// ---------------------------------------------------------------------------
#define PROW 80
#define PTL  (64 * PROW)                 // 5120 floats
#define QTL  (64 * 64)                   // 4096 floats
#define SROW 68
#define STL  (64 * SROW)                 // 4352 floats
#define ATTN_SMEM2 ((4 * PTL + 4 * QTL + 4 * STL) * 4)   // 217088 B

__global__ __launch_bounds__(512, 1) void attn_kernel() {
    extern __shared__ float smf[];
    float* pe_sm = smf;                      // [4][PTL]
    float* q_sm  = smf + 4 * PTL;            // [4][QTL]  (Q staging, later V)
    float* s_sm  = smf + 4 * PTL + 4 * QTL;  // [4][STL]

    uint32_t pe_u = smem_u32(pe_sm);
    uint32_t q_u  = smem_u32(q_sm);

    int h  = blockIdx.y;
    int b0 = blockIdx.x * 4;
    int t  = threadIdx.x;

    // phase-1 mapping
    int bp = t >> 8;          // 0..1 -> batches bp*2, bp*2+1
    int m  = (t >> 2) & 63;
    int dq = t & 3;

    float4 kreg[2][4];

    // ---- K staging round A: batches 0,1 -> pe bufs 0,1 ----
#pragma unroll
    for (int i = 0; i < 4; i++) {
        int c = t + i * 512;             // 0..2047
        int b = c >> 10;                 // 0..1
        int r = (c >> 4) & 63;
        int j = c & 15;
        cp16(pe_u + (uint32_t)((b * PTL + r * PROW) * 4 + j * 16),
             g_k + ((size_t)((b0 + b) * 64 + r)) * 512 + h * 64 + j * 4);
    }
    CP_COMMIT(); CP_WAIT(0);
    __syncthreads();
    if (bp == 0) {
#pragma unroll
        for (int bb = 0; bb < 2; bb++)
#pragma unroll
            for (int c = 0; c < 4; c++)
                kreg[bb][c] = *(const float4*)&pe_sm[bb * PTL + m * PROW + 4 * dq + 16 * c];
    }
    __syncthreads();

    // ---- K staging round B (batches 2,3 -> pe bufs 0,1) + Q staging ----
#pragma unroll
    for (int i = 0; i < 4; i++) {
        int c = t + i * 512;
        int b = c >> 10;                 // 0..1 -> batches 2,3
        int r = (c >> 4) & 63;
        int j = c & 15;
        cp16(pe_u + (uint32_t)((b * PTL + r * PROW) * 4 + j * 16),
             g_k + ((size_t)((b0 + 2 + b) * 64 + r)) * 512 + h * 64 + j * 4);
    }
#pragma unroll
    for (int i = 0; i < 8; i++) {
        int c = t + i * 512;             // 0..4095
        int b = c >> 10;                 // 0..3
        int r = (c >> 4) & 63;
        int j = c & 15;
        cp16(q_u + (uint32_t)((b * QTL + r * 64) * 4 + j * 16),
             g_q + ((size_t)((b0 + b) * 64 + r)) * 512 + h * 64 + j * 4);
    }
    CP_COMMIT(); CP_WAIT(0);
    __syncthreads();
    if (bp == 1) {
#pragma unroll
        for (int bb = 0; bb < 2; bb++)
#pragma unroll
            for (int c = 0; c < 4; c++)
                kreg[bb][c] = *(const float4*)&pe_sm[bb * PTL + m * PROW + 4 * dq + 16 * c];
    }
    __syncthreads();

    // ---- pe ring staging: buf = n & 3, 3 tiles ahead ----
    auto stage_pe = [&](int n) {
        int buf = n & 3;
#pragma unroll
        for (int i = 0; i < 2; i++) {
            int c = t + i * 512;         // 0..1023
            int r = c >> 4;
            int j = c & 15;
            cp16(pe_u + (uint32_t)((buf * PTL + r * PROW) * 4 + j * 16),
                 g_pe + ((size_t)(n * 64 + r)) * 512 + h * 64 + j * 4);
        }
        CP_COMMIT();
    };
    stage_pe(0);
    stage_pe(1);
    stage_pe(2);

    // ---- Phase 1: scores, ONE barrier per iteration ----
    for (int n = 0; n < 64; n++) {
        if (n <= 61) { CP_WAIT(2); }
        else if (n == 62) { CP_WAIT(1); }
        else { CP_WAIT(0); }
        __syncthreads();   // pe[n] visible to all; bounds skew to 1 iter

        int buf = n & 3;
        float p0 = 0.0f, p1 = 0.0f;
        const float* peb = &pe_sm[buf * PTL + m * PROW + 4 * dq];
        const float* qb0 = &q_sm[(bp * 2 + 0) * QTL + n * 64 + 4 * dq];
        const float* qb1 = &q_sm[(bp * 2 + 1) * QTL + n * 64 + 4 * dq];
#pragma unroll
        for (int c = 0; c < 4; c++) {
            float4 pe4 = *(const float4*)(peb + 16 * c);
            float4 q0  = *(const float4*)(qb0 + 16 * c);
            float4 q1  = *(const float4*)(qb1 + 16 * c);
            p0 = fmaf(q0.x * kreg[0][c].x, pe4.x, p0);
            p0 = fmaf(q0.y * kreg[0][c].y, pe4.y, p0);
            p0 = fmaf(q0.z * kreg[0][c].z, pe4.z, p0);
            p0 = fmaf(q0.w * kreg[0][c].w, pe4.w, p0);
            p1 = fmaf(q1.x * kreg[1][c].x, pe4.x, p1);
            p1 = fmaf(q1.y * kreg[1][c].y, pe4.y, p1);
            p1 = fmaf(q1.z * kreg[1][c].z, pe4.z, p1);
            p1 = fmaf(q1.w * kreg[1][c].w, pe4.w, p1);
        }
        p0 += __shfl_xor_sync(0xffffffffu, p0, 1);
        p0 += __shfl_xor_sync(0xffffffffu, p0, 2);
        p1 += __shfl_xor_sync(0xffffffffu, p1, 1);
        p1 += __shfl_xor_sync(0xffffffffu, p1, 2);
        if (dq == 0) {
            s_sm[(bp * 2 + 0) * STL + n * SROW + m] = p0 * 0.125f;
            s_sm[(bp * 2 + 1) * STL + n * SROW + m] = p1 * 0.125f;
        }
        if (n + 3 < 64) stage_pe(n + 3);
    }
    __syncthreads();   // all scores written before softmax / V staging

    // ---- stage V (4 batches) into q_sm (free after phase 1) ----
#pragma unroll
    for (int i = 0; i < 8; i++) {
        int c = t + i * 512;             // 0..4095
        int b = c >> 10;
        int r = (c >> 4) & 63;
        int j = c & 15;
        cp16(q_u + (uint32_t)((b * QTL + r * 64) * 4 + j * 16),
             g_v + ((size_t)((b0 + b) * 64 + r)) * 512 + h * 64 + j * 4);
    }
    CP_COMMIT();

    // ---- Phase 2: softmax, thread (b, n, half) ----
    {
        int b  = t >> 7;
        int n  = (t >> 1) & 63;
        int hf = t & 1;
        float* row = &s_sm[b * STL + n * SROW + hf * 32];
        float4 e[8];
        float mx = -1e30f;
#pragma unroll
        for (int i = 0; i < 8; i++) {
            e[i] = *(const float4*)(row + i * 4);
            mx = fmaxf(mx, fmaxf(fmaxf(e[i].x, e[i].y), fmaxf(e[i].z, e[i].w)));
        }
        mx = fmaxf(mx, __shfl_xor_sync(0xffffffffu, mx, 1));
        float sum = 0.0f;
#pragma unroll
        for (int i = 0; i < 8; i++) {
            e[i].x = __expf(e[i].x - mx); e[i].y = __expf(e[i].y - mx);
            e[i].z = __expf(e[i].z - mx); e[i].w = __expf(e[i].w - mx);
            sum += e[i].x + e[i].y + e[i].z + e[i].w;
        }
        sum += __shfl_xor_sync(0xffffffffu, sum, 1);
        float inv = 1.0f / sum;
#pragma unroll
        for (int i = 0; i < 8; i++) {
            e[i].x *= inv; e[i].y *= inv; e[i].z *= inv; e[i].w *= inv;
            *(float4*)(row + i * 4) = e[i];
        }
    }

    CP_WAIT(0);
    __syncthreads();   // V staged + softmax stores visible

    // ---- Phase 3: AV. thread (nh = t>>8, vb = (t>>6)&3, d = t&63) ----
    {
        int nh = t >> 8;
        int vb = (t >> 6) & 3;
        int d  = t & 63;

        float vreg[64];
#pragma unroll
        for (int mm = 0; mm < 64; mm++)
            vreg[mm] = q_sm[vb * QTL + mm * 64 + d];

        int n0 = nh * 32;
        for (int n = n0; n < n0 + 32; n++) {
            const float* sp = &s_sm[vb * STL + n * SROW];
            float acc = 0.0f;
#pragma unroll
            for (int c = 0; c < 16; c++) {
                float4 s4 = *(const float4*)(sp + c * 4);
                acc = fmaf(s4.x, vreg[c * 4 + 0], acc);
                acc = fmaf(s4.y, vreg[c * 4 + 1], acc);
                acc = fmaf(s4.z, vreg[c * 4 + 2], acc);
                acc = fmaf(s4.w, vreg[c * 4 + 3], acc);
            }
            g_x[((size_t)((b0 + vb) * 64 + n)) * 512 + h * 64 + d] = acc;
        }
    }
}

// ---------------------------------------------------------------------------
// Launch — MLP chain on side stream overlapping QKV:
//   main: prep ─ew─ qkv ──(wait e1)── attn ── out
//   s1:        └──── mlp1 ── mlp2 ─e1─┘
// ---------------------------------------------------------------------------
extern "C" void kernel_launch(void* const* d_in, const int* in_sizes, int n_in,
                              void* d_out, int out_size)
{
    const float* query = (const float*)d_in[0];
    const float* qpos  = (const float*)d_in[1];
    const float* Wq    = (const float*)d_in[2];
    const float* bq    = (const float*)d_in[3];
    const float* Wk    = (const float*)d_in[4];
    const float* Wv    = (const float*)d_in[5];
    const float* bv    = (const float*)d_in[6];
    const float* Wo    = (const float*)d_in[7];
    const float* bo    = (const float*)d_in[8];
    const float* W1    = (const float*)d_in[9];
    const float* b1    = (const float*)d_in[10];
    const float* W2    = (const float*)d_in[11];
    const float* b2    = (const float*)d_in[12];
    float* out = (float*)d_out;

    static cudaStream_t s1 = nullptr;
    static cudaEvent_t ew = nullptr, e1 = nullptr;
    if (!s1) {
        cudaStreamCreateWithFlags(&s1, cudaStreamNonBlocking);
        cudaEventCreateWithFlags(&ew, cudaEventDisableTiming);
        cudaEventCreateWithFlags(&e1, cudaEventDisableTiming);
        cudaFuncSetAttribute(gemm_qkv,  cudaFuncAttributeMaxDynamicSharedMemorySize, TSMEM);
        cudaFuncSetAttribute(gemm_mlp1, cudaFuncAttributeMaxDynamicSharedMemorySize, TSMEM);
        cudaFuncSetAttribute(gemm_mlp2, cudaFuncAttributeMaxDynamicSharedMemorySize, TSMEM);
        cudaFuncSetAttribute(gemm_out,  cudaFuncAttributeMaxDynamicSharedMemorySize, TSMEM);
        cudaFuncSetAttribute(attn_kernel, cudaFuncAttributeMaxDynamicSharedMemorySize, ATTN_SMEM2);
    }

    // prep on main stream
    prep_kernel<<<PREP_BLOCKS, 256>>>(qpos, W1, W2, Wq, Wk, Wv, Wo, bq, bv);
    cudaEventRecord(ew, 0);

    // side stream: pe MLP chain (32 us) hidden under QKV (64 us)
    cudaStreamWaitEvent(s1, ew, 0);
    gemm_mlp1<<<256, 256, TSMEM, s1>>>(b1);
    gemm_mlp2<<<256, 256, TSMEM, s1>>>(b2);
    cudaEventRecord(e1, s1);

    // main stream: QKV
    gemm_qkv<<<768, 256, TSMEM>>>(query);

    // join -> attention -> output projection
    cudaStreamWaitEvent(0, e1, 0);
    attn_kernel<<<dim3(16, HH), 512, ATTN_SMEM2>>>();
    gemm_out<<<256, 256, TSMEM>>>(bo, query, out);
}

// round 15
// speedup vs baseline: 2.0227x; 1.0050x over previous
#include <cuda_runtime.h>
#include <math.h>
#include <stdint.h>

// Problem constants
#define BB    64
#define CC    512
#define HH    8
#define HD    64
#define FREQE 256
#define ROWS  4096   // B*N == N*M
#define WSLOT (CC * CC)

// ---------------------------------------------------------------------------
// Scratch (device globals; no allocation allowed)
// ---------------------------------------------------------------------------
__device__ float g_pe [ROWS * CC];
__device__ float g_q  [ROWS * CC];
__device__ float g_k  [ROWS * CC];
__device__ float g_v  [ROWS * CC];
__device__ float g_x  [ROWS * CC];
__device__ float g_emb[ROWS * FREQE];
__device__ float g_hid[ROWS * CC];
__device__ float g_bqkv[3 * CC];
__device__ float g_wt [6 * CC * CC];    // transposed W1,W2,Wq,Wk,Wv,Wo (fp32)

__device__ __forceinline__ uint32_t to_tf32(float x) {
    uint32_t u;
    asm("cvt.rna.tf32.f32 %0, %1;" : "=r"(u) : "f"(x));
    return u;
}

__device__ __forceinline__ uint32_t smem_u32(const void* p) {
    uint32_t a;
    asm("{ .reg .u64 t; cvta.to.shared.u64 t, %1; cvt.u32.u64 %0, t; }"
        : "=r"(a) : "l"(p));
    return a;
}

__device__ __forceinline__ void cp16(uint32_t dst, const void* src) {
    asm volatile("cp.async.cg.shared.global [%0], [%1], 16;" :: "r"(dst), "l"(src));
}
#define CP_COMMIT() asm volatile("cp.async.commit_group;" ::: "memory")
#define CP_WAIT(n)  asm volatile("cp.async.wait_group %0;" :: "n"(n) : "memory")

// ---------------------------------------------------------------------------
// prep: embedding + 6 weight transposes + fused qkv bias.
// ---------------------------------------------------------------------------
#define PREP_BLOCKS (4096 + 1536 + 6)

__global__ __launch_bounds__(256) void prep_kernel(
    const float* __restrict__ qpos,
    const float* __restrict__ W1, const float* __restrict__ W2,
    const float* __restrict__ Wq, const float* __restrict__ Wk,
    const float* __restrict__ Wv, const float* __restrict__ Wo,
    const float* __restrict__ bq, const float* __restrict__ bv)
{
    int bid = blockIdx.x;
    int t = threadIdx.x;

    if (bid < 4096) {                       // embedding (fast-math)
        int idx = bid * 256 + t;
        int p = idx >> 8;
        int j = idx & 255;
        float tp = qpos[p];
        int jj = j & 127;
        float f = __expf(-9.210340371976184f * (float)jj * (1.0f / 128.0f));
        float a = tp * f;
        float s, c;
        __sincosf(a, &s, &c);
        g_emb[idx] = (j < 128) ? c : s;
        return;
    }
    if (bid < 5632) {                       // weight transposes
        int bid2 = bid - 4096;
        int slot = bid2 >> 8;               // 0..5
        int r    = bid2 & 255;
        int k0 = (r & 15) * 32;
        int n0 = (r >> 4) * 32;
        int K = (slot == 0) ? FREQE : CC;
        if (k0 >= K) return;

        const float* W = (slot == 0) ? W1 : (slot == 1) ? W2 : (slot == 2) ? Wq
                       : (slot == 3) ? Wk : (slot == 4) ? Wv : Wo;

        __shared__ float sm[32][33];
        int tx = t & 31, ty = t >> 5;
#pragma unroll
        for (int i = 0; i < 4; i++) {
            int rr = ty + i * 8;
            sm[rr][tx] = W[(size_t)(k0 + rr) * CC + n0 + tx];
        }
        __syncthreads();
#pragma unroll
        for (int i = 0; i < 4; i++) {
            int rr = ty + i * 8;
            g_wt[(size_t)slot * WSLOT + (size_t)(n0 + rr) * K + k0 + tx] = sm[tx][rr];
        }
        return;
    }
    {                                       // bias fuse
        int i = (bid - 5632) * 256 + t;
        float v = 0.0f;
        if (i < 512) v = bq[i];
        else if (i >= 1024) v = bv[i - 1024];
        g_bqkv[i] = v;
    }
}

// ---------------------------------------------------------------------------
// 1xTF32 GEMM: CTA tile 128x128, BK=32, 4 warps (128 thr), warp tile 64x64.
// 32 MMAs per warp per k8-step -> ~3.3 issue slots per MMA.
// epi: 0=+bias ; 1=silu(+bias) ; 2=+bias+resid ; 3=QKV split {Cf,C2,C3}
// ---------------------------------------------------------------------------
#define TPAD 36
#define GTILE (128 * TPAD * 4)          // 18432 B per tile
#define TSMEM (4 * GTILE)               // A,B x 2 stages = 73728 B

#define MMA1688T(d, a, b) \
    asm volatile( \
        "mma.sync.aligned.m16n8k8.row.col.f32.tf32.tf32.f32 " \
        "{%0,%1,%2,%3}, {%4,%5,%6,%7}, {%8,%9}, {%0,%1,%2,%3};" \
        : "+f"((d)[0]), "+f"((d)[1]), "+f"((d)[2]), "+f"((d)[3]) \
        : "r"((a)[0]), "r"((a)[1]), "r"((a)[2]), "r"((a)[3]), \
          "r"((b)[0]), "r"((b)[1]))

__device__ __forceinline__ void gemm_body(
    const float* __restrict__ A, const float* __restrict__ Bt,
    const float* __restrict__ bias, const float* __restrict__ resid,
    float* __restrict__ Cf, float* __restrict__ C2, float* __restrict__ C3,
    int K, int epi, int bx, int by, float* smf)
{
    uint32_t sbase = smem_u32(smf);
    int t = threadIdx.x, lane = t & 31, wid = t >> 5;   // 4 warps
    int wm = wid >> 1;        // 0..1 -> m offset wm*64
    int wn = wid & 1;         // 0..1 -> n offset wn*64
    int m0 = by * 128, n0 = bx * 128;
    int gr = lane >> 2, gc = lane & 3;

    float acc[4][8][4];
#pragma unroll
    for (int mi = 0; mi < 4; mi++)
#pragma unroll
        for (int ni = 0; ni < 8; ni++)
#pragma unroll
            for (int j = 0; j < 4; j++) acc[mi][ni][j] = 0.0f;

    int nch = K >> 5;

    auto load_chunk = [&](int ch, int buf) {
        int k0 = ch << 5;
#pragma unroll
        for (int i = 0; i < 8; i++) {       // A: 128 rows x 8 chunks = 1024 slots
            int idx = t + i * 128;
            int row = idx >> 3;
            int c   = idx & 7;
            uint32_t off = (uint32_t)(row * TPAD * 4 + c * 16);
            cp16(sbase + buf * GTILE + off,
                 A + (size_t)(m0 + row) * K + k0 + c * 4);
        }
#pragma unroll
        for (int i = 0; i < 8; i++) {       // B: 128 rows x 8 chunks
            int idx = t + i * 128;
            int row = idx >> 3;
            int c   = idx & 7;
            uint32_t off = (uint32_t)(row * TPAD * 4 + c * 16);
            cp16(sbase + 2 * GTILE + buf * GTILE + off,
                 Bt + (size_t)(n0 + row) * K + k0 + c * 4);
        }
        CP_COMMIT();
    };

    load_chunk(0, 0);
    load_chunk(1, 1);

    for (int ch = 0; ch < nch; ch++) {
        if (ch + 1 < nch) { CP_WAIT(1); } else { CP_WAIT(0); }
        __syncthreads();

        int buf = ch & 1;
        const float* sA = smf + (buf * GTILE >> 2);
        const float* sB = smf + ((2 * GTILE + buf * GTILE) >> 2);

#pragma unroll
        for (int ks = 0; ks < 4; ks++) {
            int kk = ks * 8;
            uint32_t af[4][4], bf[8][2];
#pragma unroll
            for (int mi = 0; mi < 4; mi++) {
                int base = (wm * 64 + mi * 16 + gr) * TPAD + kk;
                af[mi][0] = to_tf32(sA[base + gc]);
                af[mi][1] = to_tf32(sA[base + 8 * TPAD + gc]);
                af[mi][2] = to_tf32(sA[base + gc + 4]);
                af[mi][3] = to_tf32(sA[base + 8 * TPAD + gc + 4]);
            }
#pragma unroll
            for (int ni = 0; ni < 8; ni++) {
                int base = (wn * 64 + ni * 8 + gr) * TPAD + kk;
                bf[ni][0] = to_tf32(sB[base + gc]);
                bf[ni][1] = to_tf32(sB[base + gc + 4]);
            }
#pragma unroll
            for (int mi = 0; mi < 4; mi++)
#pragma unroll
                for (int ni = 0; ni < 8; ni++)
                    MMA1688T(acc[mi][ni], af[mi], bf[ni]);
        }
        __syncthreads();
        if (ch + 2 < nch) load_chunk(ch + 2, buf);
    }

    // Epilogue
#pragma unroll
    for (int mi = 0; mi < 4; mi++) {
#pragma unroll
        for (int ni = 0; ni < 8; ni++) {
            int row0 = m0 + wm * 64 + mi * 16 + gr;
            int col  = n0 + wn * 64 + ni * 8 + gc * 2;
#pragma unroll
            for (int half = 0; half < 2; half++) {
                int row = row0 + half * 8;
                float v0 = acc[mi][ni][half * 2 + 0];
                float v1 = acc[mi][ni][half * 2 + 1];
                if (bias) { v0 += bias[col]; v1 += bias[col + 1]; }
                if (epi == 1) {
                    v0 = v0 / (1.0f + expf(-v0));
                    v1 = v1 / (1.0f + expf(-v1));
                }
                if (epi == 3) {
                    int seg = col >> 9;
                    float* dst = (seg == 0) ? Cf : (seg == 1) ? C2 : C3;
                    size_t o = (size_t)row * CC + (col & 511);
                    *(float2*)(dst + o) = make_float2(v0, v1);
                } else {
                    size_t o = (size_t)row * CC + col;
                    if (epi == 2) {
                        v0 += resid[o];
                        v1 += resid[o + 1];
                    }
                    *(float2*)(Cf + o) = make_float2(v0, v1);
                }
            }
        }
    }
}

// QKV GEMM: grid 12 x 32 = 384 blocks
__global__ __launch_bounds__(128, 2) void gemm_qkv(const float* __restrict__ query)
{
    extern __shared__ float smf[];
    int bid = blockIdx.x;
    gemm_body(query, g_wt + 2 * WSLOT, g_bqkv, nullptr,
              g_q, g_k, g_v, CC, 3, bid % 12, bid / 12, smf);
}

// MLP1: grid 4 x 32 = 128 blocks
__global__ __launch_bounds__(128, 2) void gemm_mlp1(const float* __restrict__ b1)
{
    extern __shared__ float smf[];
    int bid = blockIdx.x;
    gemm_body(g_emb, g_wt + 0 * WSLOT, b1, nullptr,
              g_hid, nullptr, nullptr, FREQE, 1, bid & 3, bid >> 2, smf);
}

// MLP2: 128 blocks
__global__ __launch_bounds__(128, 2) void gemm_mlp2(const float* __restrict__ b2)
{
    extern __shared__ float smf[];
    int bid = blockIdx.x;
    gemm_body(g_hid, g_wt + 1 * WSLOT, b2, nullptr,
              g_pe, nullptr, nullptr, CC, 0, bid & 3, bid >> 2, smf);
}

// output projection + bias + residual: 128 blocks
__global__ __launch_bounds__(128, 2) void gemm_out(
    const float* __restrict__ bo, const float* __restrict__ query,
    float* __restrict__ out)
{
    extern __shared__ float smf[];
    int bid = blockIdx.x;
    gemm_body(g_x, g_wt + 5 * WSLOT, bo, query,
              out, nullptr, nullptr, CC, 2, bid & 3, bid >> 2, smf);
}

// ---------------------------------------------------------------------------
// Attention: 4 batches/block, 512 threads, 1 CTA/SM, grid (16, 8).
// pe ring buffer x4 (PROW=80, conflict-free) -> ONE barrier per n-iteration.
// smem: pe[4][PTL] | q[4][QTL] | s[4][STL] = 212 KB.
// ---------------------------------------------------------------------------
#define PROW 80
#define PTL  (64 * PROW)                 // 5120 floats
#define QTL  (64 * 64)                   // 4096 floats
#define SROW 68
#define STL  (64 * SROW)                 // 4352 floats
#define ATTN_SMEM2 ((4 * PTL + 4 * QTL + 4 * STL) * 4)   // 217088 B

__global__ __launch_bounds__(512, 1) void attn_kernel() {
    extern __shared__ float smf[];
    float* pe_sm = smf;                      // [4][PTL]
    float* q_sm  = smf + 4 * PTL;            // [4][QTL]  (Q staging, later V)
    float* s_sm  = smf + 4 * PTL + 4 * QTL;  // [4][STL]

    uint32_t pe_u = smem_u32(pe_sm);
    uint32_t q_u  = smem_u32(q_sm);

    int h  = blockIdx.y;
    int b0 = blockIdx.x * 4;
    int t  = threadIdx.x;

    int bp = t >> 8;          // 0..1 -> batches bp*2, bp*2+1
    int m  = (t >> 2) & 63;
    int dq = t & 3;

    float4 kreg[2][4];

    // ---- K staging round A: batches 0,1 -> pe bufs 0,1 ----
#pragma unroll
    for (int i = 0; i < 4; i++) {
        int c = t + i * 512;             // 0..2047
        int b = c >> 10;                 // 0..1
        int r = (c >> 4) & 63;
        int j = c & 15;
        cp16(pe_u + (uint32_t)((b * PTL + r * PROW) * 4 + j * 16),
             g_k + ((size_t)((b0 + b) * 64 + r)) * 512 + h * 64 + j * 4);
    }
    CP_COMMIT(); CP_WAIT(0);
    __syncthreads();
    if (bp == 0) {
#pragma unroll
        for (int bb = 0; bb < 2; bb++)
#pragma unroll
            for (int c = 0; c < 4; c++)
                kreg[bb][c] = *(const float4*)&pe_sm[bb * PTL + m * PROW + 4 * dq + 16 * c];
    }
    __syncthreads();

    // ---- K staging round B (batches 2,3) + Q staging (all 4) ----
#pragma unroll
    for (int i = 0; i < 4; i++) {
        int c = t + i * 512;
        int b = c >> 10;
        int r = (c >> 4) & 63;
        int j = c & 15;
        cp16(pe_u + (uint32_t)((b * PTL + r * PROW) * 4 + j * 16),
             g_k + ((size_t)((b0 + 2 + b) * 64 + r)) * 512 + h * 64 + j * 4);
    }
#pragma unroll
    for (int i = 0; i < 8; i++) {
        int c = t + i * 512;             // 0..4095
        int b = c >> 10;
        int r = (c >> 4) & 63;
        int j = c & 15;
        cp16(q_u + (uint32_t)((b * QTL + r * 64) * 4 + j * 16),
             g_q + ((size_t)((b0 + b) * 64 + r)) * 512 + h * 64 + j * 4);
    }
    CP_COMMIT(); CP_WAIT(0);
    __syncthreads();
    if (bp == 1) {
#pragma unroll
        for (int bb = 0; bb < 2; bb++)
#pragma unroll
            for (int c = 0; c < 4; c++)
                kreg[bb][c] = *(const float4*)&pe_sm[bb * PTL + m * PROW + 4 * dq + 16 * c];
    }
    __syncthreads();

    // ---- pe ring staging: buf = n & 3, 3 tiles ahead ----
    auto stage_pe = [&](int n) {
        int buf = n & 3;
#pragma unroll
        for (int i = 0; i < 2; i++) {
            int c = t + i * 512;         // 0..1023
            int r = c >> 4;
            int j = c & 15;
            cp16(pe_u + (uint32_t)((buf * PTL + r * PROW) * 4 + j * 16),
                 g_pe + ((size_t)(n * 64 + r)) * 512 + h * 64 + j * 4);
        }
        CP_COMMIT();
    };
    stage_pe(0);
    stage_pe(1);
    stage_pe(2);

    // ---- Phase 1: scores, ONE barrier per iteration ----
    for (int n = 0; n < 64; n++) {
        if (n <= 61) { CP_WAIT(2); }
        else if (n == 62) { CP_WAIT(1); }
        else { CP_WAIT(0); }
        __syncthreads();

        int buf = n & 3;
        float p0 = 0.0f, p1 = 0.0f;
        const float* peb = &pe_sm[buf * PTL + m * PROW + 4 * dq];
        const float* qb0 = &q_sm[(bp * 2 + 0) * QTL + n * 64 + 4 * dq];
        const float* qb1 = &q_sm[(bp * 2 + 1) * QTL + n * 64 + 4 * dq];
#pragma unroll
        for (int c = 0; c < 4; c++) {
            float4 pe4 = *(const float4*)(peb + 16 * c);
            float4 q0  = *(const float4*)(qb0 + 16 * c);
            float4 q1  = *(const float4*)(qb1 + 16 * c);
            p0 = fmaf(q0.x * kreg[0][c].x, pe4.x, p0);
            p0 = fmaf(q0.y * kreg[0][c].y, pe4.y, p0);
            p0 = fmaf(q0.z * kreg[0][c].z, pe4.z, p0);
            p0 = fmaf(q0.w * kreg[0][c].w, pe4.w, p0);
            p1 = fmaf(q1.x * kreg[1][c].x, pe4.x, p1);
            p1 = fmaf(q1.y * kreg[1][c].y, pe4.y, p1);
            p1 = fmaf(q1.z * kreg[1][c].z, pe4.z, p1);
            p1 = fmaf(q1.w * kreg[1][c].w, pe4.w, p1);
        }
        p0 += __shfl_xor_sync(0xffffffffu, p0, 1);
        p0 += __shfl_xor_sync(0xffffffffu, p0, 2);
        p1 += __shfl_xor_sync(0xffffffffu, p1, 1);
        p1 += __shfl_xor_sync(0xffffffffu, p1, 2);
        if (dq == 0) {
            s_sm[(bp * 2 + 0) * STL + n * SROW + m] = p0 * 0.125f;
            s_sm[(bp * 2 + 1) * STL + n * SROW + m] = p1 * 0.125f;
        }
        if (n + 3 < 64) stage_pe(n + 3);
    }
    __syncthreads();

    // ---- stage V (4 batches) into q_sm ----
#pragma unroll
    for (int i = 0; i < 8; i++) {
        int c = t + i * 512;             // 0..4095
        int b = c >> 10;
        int r = (c >> 4) & 63;
        int j = c & 15;
        cp16(q_u + (uint32_t)((b * QTL + r * 64) * 4 + j * 16),
             g_v + ((size_t)((b0 + b) * 64 + r)) * 512 + h * 64 + j * 4);
    }
    CP_COMMIT();

    // ---- Phase 2: softmax, thread (b, n, half) ----
    {
        int b  = t >> 7;
        int n  = (t >> 1) & 63;
        int hf = t & 1;
        float* row = &s_sm[b * STL + n * SROW + hf * 32];
        float4 e[8];
        float mx = -1e30f;
#pragma unroll
        for (int i = 0; i < 8; i++) {
            e[i] = *(const float4*)(row + i * 4);
            mx = fmaxf(mx, fmaxf(fmaxf(e[i].x, e[i].y), fmaxf(e[i].z, e[i].w)));
        }
        mx = fmaxf(mx, __shfl_xor_sync(0xffffffffu, mx, 1));
        float sum = 0.0f;
#pragma unroll
        for (int i = 0; i < 8; i++) {
            e[i].x = __expf(e[i].x - mx); e[i].y = __expf(e[i].y - mx);
            e[i].z = __expf(e[i].z - mx); e[i].w = __expf(e[i].w - mx);
            sum += e[i].x + e[i].y + e[i].z + e[i].w;
        }
        sum += __shfl_xor_sync(0xffffffffu, sum, 1);
        float inv = 1.0f / sum;
#pragma unroll
        for (int i = 0; i < 8; i++) {
            e[i].x *= inv; e[i].y *= inv; e[i].z *= inv; e[i].w *= inv;
            *(float4*)(row + i * 4) = e[i];
        }
    }

    CP_WAIT(0);
    __syncthreads();

    // ---- Phase 3: AV. thread (nh = t>>8, vb = (t>>6)&3, d = t&63) ----
    {
        int nh = t >> 8;
        int vb = (t >> 6) & 3;
        int d  = t & 63;

        float vreg[64];
#pragma unroll
        for (int mm = 0; mm < 64; mm++)
            vreg[mm] = q_sm[vb * QTL + mm * 64 + d];

        int n0 = nh * 32;
        for (int n = n0; n < n0 + 32; n++) {
            const float* sp = &s_sm[vb * STL + n * SROW];
            float acc = 0.0f;
#pragma unroll
            for (int c = 0; c < 16; c++) {
                float4 s4 = *(const float4*)(sp + c * 4);
                acc = fmaf(s4.x, vreg[c * 4 + 0], acc);
                acc = fmaf(s4.y, vreg[c * 4 + 1], acc);
                acc = fmaf(s4.z, vreg[c * 4 + 2], acc);
                acc = fmaf(s4.w, vreg[c * 4 + 3], acc);
            }
            g_x[((size_t)((b0 + vb) * 64 + n)) * 512 + h * 64 + d] = acc;
        }
    }
}

// ---------------------------------------------------------------------------
// Launch — MLP chain on side stream overlapping QKV:
//   main: prep ─ew─ qkv ──(wait e1)── attn ── out
//   s1:        └──── mlp1 ── mlp2 ─e1─┘
// ---------------------------------------------------------------------------
extern "C" void kernel_launch(void* const* d_in, const int* in_sizes, int n_in,
                              void* d_out, int out_size)
{
    const float* query = (const float*)d_in[0];
    const float* qpos  = (const float*)d_in[1];
    const float* Wq    = (const float*)d_in[2];
    const float* bq    = (const float*)d_in[3];
    const float* Wk    = (const float*)d_in[4];
    const float* Wv    = (const float*)d_in[5];
    const float* bv    = (const float*)d_in[6];
    const float* Wo    = (const float*)d_in[7];
    const float* bo    = (const float*)d_in[8];
    const float* W1    = (const float*)d_in[9];
    const float* b1    = (const float*)d_in[10];
    const float* W2    = (const float*)d_in[11];
    const float* b2    = (const float*)d_in[12];
    float* out = (float*)d_out;

    static cudaStream_t s1 = nullptr;
    static cudaEvent_t ew = nullptr, e1 = nullptr;
    if (!s1) {
        cudaStreamCreateWithFlags(&s1, cudaStreamNonBlocking);
        cudaEventCreateWithFlags(&ew, cudaEventDisableTiming);
        cudaEventCreateWithFlags(&e1, cudaEventDisableTiming);
        cudaFuncSetAttribute(gemm_qkv,  cudaFuncAttributeMaxDynamicSharedMemorySize, TSMEM);
        cudaFuncSetAttribute(gemm_mlp1, cudaFuncAttributeMaxDynamicSharedMemorySize, TSMEM);
        cudaFuncSetAttribute(gemm_mlp2, cudaFuncAttributeMaxDynamicSharedMemorySize, TSMEM);
        cudaFuncSetAttribute(gemm_out,  cudaFuncAttributeMaxDynamicSharedMemorySize, TSMEM);
        cudaFuncSetAttribute(attn_kernel, cudaFuncAttributeMaxDynamicSharedMemorySize, ATTN_SMEM2);
    }

    // prep on main stream
    prep_kernel<<<PREP_BLOCKS, 256>>>(qpos, W1, W2, Wq, Wk, Wv, Wo, bq, bv);
    cudaEventRecord(ew, 0);

    // side stream: pe MLP chain hidden under QKV
    cudaStreamWaitEvent(s1, ew, 0);
    gemm_mlp1<<<128, 128, TSMEM, s1>>>(b1);
    gemm_mlp2<<<128, 128, TSMEM, s1>>>(b2);
    cudaEventRecord(e1, s1);

    // main stream: QKV
    gemm_qkv<<<384, 128, TSMEM>>>(query);

    // join -> attention -> output projection
    cudaStreamWaitEvent(0, e1, 0);
    attn_kernel<<<dim3(16, HH), 512, ATTN_SMEM2>>>();
    gemm_out<<<128, 128, TSMEM>>>(bo, query, out);
}